// round 10
// baseline (speedup 1.0000x reference)
#include <cuda_runtime.h>
#include <cuda_bf16.h>
#include <cstdint>

// ---------------------------------------------------------------------------
// GraphAutoencoder (all-SIMT fp32, f32x2-packed FMA pipe):
//   h   = x @ W_enc                                    [N, 128]
//   deg = in-degree(dst) + 1 (self loop); dinv = rsqrt(deg)
//   enc = sum_{e:(s->d)} h[s]*dinv[s]*dinv[d] + h[i]*dinv[i]^2 + b_enc
//   out = sigmoid(enc @ W_dec + b_dec)                 [N, N]
// Decoder: accumulator pairs run over ROWS; A pairs come straight out of
// LDS.128, B is stored pre-duplicated -> mov-free FFMA2 mainloop.
// ---------------------------------------------------------------------------

#define N_NODES  10000
#define MAX_E    320000
#define IN_DIM   512
#define HID      128

__device__ __align__(16) float g_h[N_NODES * HID];
__device__ __align__(16) float g_enc[N_NODES * HID];
__device__ float g_deg[N_NODES];
__device__ float g_dinv[N_NODES];
__device__ int   g_eidx[2 * MAX_E];
__device__ int   g_is64;

// ========================== 0) edge dtype handling =========================
__global__ void detect_kernel(const void* __restrict__ e)
{
    const unsigned long long* p = (const unsigned long long*)e;
    int ok64 = 1;
    for (int i = 0; i < 128; ++i) {
        unsigned long long v = p[(size_t)i * 2499];
        if (v >= (1ull << 31)) ok64 = 0;
    }
    g_is64 = ok64;
}

// convert edges to int32 + initialize degree (self-loop = 1)
__global__ void convert_edges_kernel(const void* __restrict__ e, int E, int M)
{
    int t = blockIdx.x * blockDim.x + threadIdx.x;
    if (t < M) g_deg[t] = 1.0f;
    if (t >= 2 * E) return;
    int v;
    if (g_is64) v = (int)((const long long*)e)[t];
    else        v = ((const int*)e)[t];
    g_eidx[t] = v;
}

// ========================== 2) normalization ===============================
__global__ void deg_count_kernel(int E)
{
    int t = blockIdx.x * blockDim.x + threadIdx.x;
    if (t >= E) return;
    int d = g_eidx[E + t];
    if (d >= 0 && d < N_NODES) atomicAdd(&g_deg[d], 1.0f);
}
__global__ void dinv_kernel(int M)
{
    int i = blockIdx.x * blockDim.x + threadIdx.x;
    if (i < M) g_dinv[i] = rsqrtf(g_deg[i]);
}
__global__ void enc_init_kernel(const float* __restrict__ b_enc, int M)
{
    int t = blockIdx.x * blockDim.x + threadIdx.x;
    if (t >= M * HID) return;
    int i = t >> 7;
    int j = t & (HID - 1);
    float di = g_dinv[i];
    g_enc[t] = g_h[t] * di * di + b_enc[j];
}

// ========================== 4) edge scatter ================================
__global__ void scatter_kernel(int E)
{
    int warp = (blockIdx.x * blockDim.x + threadIdx.x) >> 5;
    int lane = threadIdx.x & 31;
    if (warp >= E) return;
    int s = g_eidx[warp];
    int d = g_eidx[E + warp];
    if ((unsigned)s >= N_NODES || (unsigned)d >= N_NODES) return;
    float norm = g_dinv[s] * g_dinv[d];
    float4 v = reinterpret_cast<const float4*>(g_h)[(size_t)s * (HID / 4) + lane];
    float* p = g_enc + (size_t)d * HID + lane * 4;
    asm volatile("red.global.add.v4.f32 [%0], {%1, %2, %3, %4};"
                 :: "l"(p), "f"(v.x * norm), "f"(v.y * norm),
                    "f"(v.z * norm), "f"(v.w * norm)
                 : "memory");
}

// ========================== 1) encoder GEMM (f32x2 tiled) ==================
#define EN_BK 8
__global__ __launch_bounds__(256)
void encode_gemm_kernel(const float* __restrict__ A,   // x
                        const float* __restrict__ B,   // W_enc
                        int M)
{
    __shared__ float As[EN_BK][128];
    __shared__ float Bs[EN_BK][128];

    const int tid = threadIdx.x;
    const int m0  = blockIdx.y * 128;

    const int aRow = tid >> 1;
    const int aCol = (tid & 1) * 4;
    const int bRow = tid >> 5;
    const int bCol = (tid & 31) * 4;
    const int tr = tid >> 4;
    const int tc = tid & 15;
    const bool aOK = (m0 + aRow < M);

    unsigned long long acc[8][4];
#pragma unroll
    for (int i = 0; i < 8; ++i)
#pragma unroll
        for (int j = 0; j < 4; ++j) acc[i][j] = 0ull;

    for (int kk = 0; kk < IN_DIM; kk += EN_BK) {
        float4 av = make_float4(0.f, 0.f, 0.f, 0.f);
        if (aOK)
            av = *reinterpret_cast<const float4*>(
                     &A[(size_t)(m0 + aRow) * IN_DIM + kk + aCol]);
        As[aCol + 0][aRow] = av.x;
        As[aCol + 1][aRow] = av.y;
        As[aCol + 2][aRow] = av.z;
        As[aCol + 3][aRow] = av.w;
        float4 bv = *reinterpret_cast<const float4*>(
                        &B[(size_t)(kk + bRow) * HID + bCol]);
        *reinterpret_cast<float4*>(&Bs[bRow][bCol]) = bv;
        __syncthreads();

#pragma unroll
        for (int k = 0; k < EN_BK; ++k) {
            float4 a0 = *reinterpret_cast<const float4*>(&As[k][tr * 8]);
            float4 a1 = *reinterpret_cast<const float4*>(&As[k][tr * 8 + 4]);
            float4 b0 = *reinterpret_cast<const float4*>(&Bs[k][tc * 8]);
            float4 b1 = *reinterpret_cast<const float4*>(&Bs[k][tc * 8 + 4]);
            unsigned long long bp[4];
            asm("mov.b64 %0, {%1, %2};" : "=l"(bp[0]) : "f"(b0.x), "f"(b0.y));
            asm("mov.b64 %0, {%1, %2};" : "=l"(bp[1]) : "f"(b0.z), "f"(b0.w));
            asm("mov.b64 %0, {%1, %2};" : "=l"(bp[2]) : "f"(b1.x), "f"(b1.y));
            asm("mov.b64 %0, {%1, %2};" : "=l"(bp[3]) : "f"(b1.z), "f"(b1.w));
            float a[8] = {a0.x, a0.y, a0.z, a0.w, a1.x, a1.y, a1.z, a1.w};
#pragma unroll
            for (int i = 0; i < 8; ++i) {
                unsigned long long ap;
                asm("mov.b64 %0, {%1, %2};" : "=l"(ap) : "f"(a[i]), "f"(a[i]));
#pragma unroll
                for (int j = 0; j < 4; ++j)
                    asm("fma.rn.f32x2 %0, %1, %2, %0;"
                        : "+l"(acc[i][j]) : "l"(ap), "l"(bp[j]));
            }
        }
        __syncthreads();
    }

#pragma unroll
    for (int i = 0; i < 8; ++i) {
        int row = m0 + tr * 8 + i;
        if (row >= M) continue;
        float v[8];
#pragma unroll
        for (int j = 0; j < 4; ++j) {
            float lo, hi;
            asm("mov.b64 {%0, %1}, %2;" : "=f"(lo), "=f"(hi) : "l"(acc[i][j]));
            v[2 * j] = lo; v[2 * j + 1] = hi;
        }
        size_t base = (size_t)row * HID + tc * 8;
        *reinterpret_cast<float4*>(&g_h[base]) =
            make_float4(v[0], v[1], v[2], v[3]);
        *reinterpret_cast<float4*>(&g_h[base + 4]) =
            make_float4(v[4], v[5], v[6], v[7]);
    }
}

// ========================== 5) decoder GEMM (f32x2, row-paired) ============
// out = sigmoid(enc @ W_dec + b_dec).  BM=BN=128, K=128 staged once.
// As[k][m] floats (64 KB): LDS.128 yields A row-pairs directly (no movs).
// Bs2 (128 KB): u64 dup-pairs (b,b), layout [k][jp][tc][h], j = 2*jp+h:
//   mainloop B = 4x LDS.128, 16 distinct 16B addrs/warp (2-thread bcast),
//   conflict-free.  FMA loop j-outer/i-inner so bp[j] gets .reuse.
__global__ __launch_bounds__(256, 1)
void decode_kernel(const float* __restrict__ Wd,
                   const float* __restrict__ bd,
                   float* __restrict__ out,
                   int M, int N)
{
    extern __shared__ float dsm[];
    float              (*As)[128] = (float(*)[128])dsm;            // [128][128]
    unsigned long long* Bs2 = (unsigned long long*)(dsm + 128 * 128);

    const int tid = threadIdx.x;
    const int m0  = blockIdx.y * 128;
    const int n0  = blockIdx.x * 128;
    const int tr  = tid >> 4;
    const int tc  = tid & 15;
    const bool fullN = (n0 + 128 <= N);

    // --- stage A (transpose): thread -> row m=tid>>1, half (tid&1)*4 ---
    {
        const int m   = tid >> 1;
        const int cb  = (tid & 1) * 4;
        const bool ok = (m0 + m < M);
        const float* src = &g_enc[(size_t)(m0 + m) * HID];
#pragma unroll
        for (int kk = 0; kk < 16; ++kk) {
            int col = kk * 8 + cb;
            float4 av = make_float4(0.f, 0.f, 0.f, 0.f);
            if (ok) av = *reinterpret_cast<const float4*>(src + col);
            As[col + 0][m] = av.x;
            As[col + 1][m] = av.y;
            As[col + 2][m] = av.z;
            As[col + 3][m] = av.w;
        }
    }
    // --- stage B as duplicated u64 pairs ---
    // float4 covers local cols c = q*4 .. q*4+3  (q = idx4 & 31, k = idx4>>5)
    // write dup(v) at u64 index  k*128 + (c&7)>>1 * 32 + (c>>3)*2 + (c&1)
#pragma unroll
    for (int jj = 0; jj < 16; ++jj) {
        int idx4 = jj * 256 + tid;        // 4096 float4 total
        int k    = idx4 >> 5;
        int q    = idx4 & 31;
        float4 bv;
        if (fullN) {
            bv = *reinterpret_cast<const float4*>(
                     &Wd[(size_t)k * N + n0 + q * 4]);
        } else {
            float t[4];
#pragma unroll
            for (int i = 0; i < 4; ++i) {
                int c = n0 + q * 4 + i;
                t[i] = (c < N) ? Wd[(size_t)k * N + c] : 0.f;
            }
            bv = make_float4(t[0], t[1], t[2], t[3]);
        }
        float v[4] = {bv.x, bv.y, bv.z, bv.w};
#pragma unroll
        for (int i = 0; i < 4; ++i) {
            int c  = q * 4 + i;           // local col 0..127
            int tcc = c >> 3;
            int j   = c & 7;
            unsigned long long dupv;
            asm("mov.b64 %0, {%1, %1};" : "=l"(dupv) : "f"(v[i]));
            Bs2[k * 128 + (j >> 1) * 32 + tcc * 2 + (j & 1)] = dupv;
        }
    }
    __syncthreads();

    // --- mainloop: 128 k-steps, mov-free ---
    unsigned long long acc[4][8];     // [row-pair ip][col j]
#pragma unroll
    for (int i = 0; i < 4; ++i)
#pragma unroll
        for (int j = 0; j < 8; ++j) acc[i][j] = 0ull;

#pragma unroll 4
    for (int k = 0; k < 128; ++k) {
        ulonglong2 a01 = *reinterpret_cast<const ulonglong2*>(&As[k][tr * 8]);
        ulonglong2 a23 = *reinterpret_cast<const ulonglong2*>(&As[k][tr * 8 + 4]);
        unsigned long long ap[4] = {a01.x, a01.y, a23.x, a23.y};

        const unsigned long long* bb = Bs2 + k * 128 + tc * 2;
        ulonglong2 b01 = *reinterpret_cast<const ulonglong2*>(bb);
        ulonglong2 b23 = *reinterpret_cast<const ulonglong2*>(bb + 32);
        ulonglong2 b45 = *reinterpret_cast<const ulonglong2*>(bb + 64);
        ulonglong2 b67 = *reinterpret_cast<const ulonglong2*>(bb + 96);
        unsigned long long bp[8] = {b01.x, b01.y, b23.x, b23.y,
                                    b45.x, b45.y, b67.x, b67.y};
#pragma unroll
        for (int j = 0; j < 8; ++j)
#pragma unroll
            for (int i = 0; i < 4; ++i)
                asm("fma.rn.f32x2 %0, %1, %2, %0;"
                    : "+l"(acc[i][j]) : "l"(ap[i]), "l"(bp[j]));
    }

    // --- epilogue: bias + sigmoid ---
    float bdv[8];
#pragma unroll
    for (int j = 0; j < 8; ++j) {
        int c = n0 + tc * 8 + j;
        bdv[j] = (c < N) ? __ldg(bd + c) : 0.f;
    }
#pragma unroll
    for (int ip = 0; ip < 4; ++ip) {
        float lo[8], hi[8];
#pragma unroll
        for (int j = 0; j < 8; ++j) {
            asm("mov.b64 {%0, %1}, %2;"
                : "=f"(lo[j]), "=f"(hi[j]) : "l"(acc[ip][j]));
        }
        int row0 = m0 + tr * 8 + ip * 2;
        int row1 = row0 + 1;
#pragma unroll
        for (int j = 0; j < 8; ++j) {
            float t0 = lo[j] + bdv[j];
            float t1 = hi[j] + bdv[j];
            lo[j] = __fdividef(1.0f, 1.0f + __expf(-t0));
            hi[j] = __fdividef(1.0f, 1.0f + __expf(-t1));
        }
        if (row0 < M) {
            size_t base = (size_t)row0 * N + n0 + tc * 8;
            if (fullN) {
                *reinterpret_cast<float4*>(&out[base]) =
                    make_float4(lo[0], lo[1], lo[2], lo[3]);
                *reinterpret_cast<float4*>(&out[base + 4]) =
                    make_float4(lo[4], lo[5], lo[6], lo[7]);
            } else {
#pragma unroll
                for (int j = 0; j < 8; ++j) {
                    int c = n0 + tc * 8 + j;
                    if (c < N) out[(size_t)row0 * N + c] = lo[j];
                }
            }
        }
        if (row1 < M) {
            size_t base = (size_t)row1 * N + n0 + tc * 8;
            if (fullN) {
                *reinterpret_cast<float4*>(&out[base]) =
                    make_float4(hi[0], hi[1], hi[2], hi[3]);
                *reinterpret_cast<float4*>(&out[base + 4]) =
                    make_float4(hi[4], hi[5], hi[6], hi[7]);
            } else {
#pragma unroll
                for (int j = 0; j < 8; ++j) {
                    int c = n0 + tc * 8 + j;
                    if (c < N) out[(size_t)row1 * N + c] = hi[j];
                }
            }
        }
    }
}

#define DEC_SMEM_BYTES (128 * 128 * 4 + 128 * 128 * 8)   // 196608

// ========================== launch =========================================
extern "C" void kernel_launch(void* const* d_in, const int* in_sizes, int n_in,
                              void* d_out, int out_size)
{
    const float* x     = (const float*)d_in[0];
    const void*  ei    = d_in[1];
    const float* W_enc = (const float*)d_in[2];
    const float* b_enc = (const float*)d_in[3];
    const float* W_dec = (const float*)d_in[4];
    const float* b_dec = (const float*)d_in[5];
    float*       out   = (float*)d_out;

    const int M = in_sizes[5];        // 10000
    int E = in_sizes[1] / 2;          // 320000
    if (E > MAX_E) E = MAX_E;

    detect_kernel<<<1, 1>>>(ei);
    convert_edges_kernel<<<(2 * E + 255) / 256, 256>>>(ei, E, M);

    {   // encoder GEMM
        dim3 grid(1, (M + 127) / 128);
        encode_gemm_kernel<<<grid, 256>>>(x, W_enc, M);
    }
    deg_count_kernel<<<(E + 255) / 256, 256>>>(E);
    dinv_kernel     <<<(M + 255) / 256, 256>>>(M);
    enc_init_kernel <<<(M * HID + 255) / 256, 256>>>(b_enc, M);
    {
        int wpb = 256 / 32;
        scatter_kernel<<<(E + wpb - 1) / wpb, 256>>>(E);
    }
    {
        static int smem_set = 0;
        if (!smem_set) {
            cudaFuncSetAttribute(decode_kernel,
                                 cudaFuncAttributeMaxDynamicSharedMemorySize,
                                 DEC_SMEM_BYTES);
            smem_set = 1;
        }
        dim3 grid((M + 127) / 128, (M + 127) / 128);
        decode_kernel<<<grid, 256, DEC_SMEM_BYTES>>>(W_dec, b_dec, out, M, M);
    }
}

// round 11
// speedup vs baseline: 1.0253x; 1.0253x over previous
#include <cuda_runtime.h>
#include <cuda_bf16.h>
#include <cstdint>

// ---------------------------------------------------------------------------
// GraphAutoencoder (all-SIMT fp32, f32x2-packed FMA pipe):
//   h   = x @ W_enc                                    [N, 128]
//   deg = in-degree(dst) + 1 (self loop); dinv = rsqrt(deg)
//   enc = sum_{e:(s->d)} h[s]*dinv[s]*dinv[d] + h[i]*dinv[i]^2 + b_enc
//   out = sigmoid(enc @ W_dec + b_dec)                 [N, N]
// Decode is FFMA2-issue-bound (rt=3 RF banking) and at its floor; this round
// removes the L2-atomic aggregation (counting sort + register gather-reduce)
// and doubles encoder occupancy (BM=64).
// ---------------------------------------------------------------------------

#define N_NODES  10000
#define MAX_E    320000
#define IN_DIM   512
#define HID      128
#define SCAN_PT  16            // elements per thread in scan (covers 16384)

__device__ __align__(16) float g_h[N_NODES * HID];
__device__ __align__(16) float g_enc[N_NODES * HID];
__device__ float g_dinv[N_NODES];
__device__ int   g_degi[N_NODES];
__device__ int   g_off[N_NODES + 1];
__device__ int   g_cursor[N_NODES];
__device__ int   g_eidx[2 * MAX_E];
__device__ int   g_esorted[MAX_E];
__device__ int   g_is64;

// ========================== 0) edge dtype handling =========================
__global__ void detect_kernel(const void* __restrict__ e)
{
    const unsigned long long* p = (const unsigned long long*)e;
    int ok64 = 1;
    for (int i = 0; i < 128; ++i) {
        unsigned long long v = p[(size_t)i * 2499];
        if (v >= (1ull << 31)) ok64 = 0;
    }
    g_is64 = ok64;
}

// convert edges to int32 + zero integer degree
__global__ void convert_edges_kernel(const void* __restrict__ e, int E, int M)
{
    int t = blockIdx.x * blockDim.x + threadIdx.x;
    if (t < M) g_degi[t] = 0;
    if (t >= 2 * E) return;
    int v;
    if (g_is64) v = (int)((const long long*)e)[t];
    else        v = ((const int*)e)[t];
    g_eidx[t] = v;
}

// ========================== 2a) integer degree count =======================
__global__ void deg_count_kernel(int E)
{
    int t = blockIdx.x * blockDim.x + threadIdx.x;
    if (t >= E) return;
    int d = g_eidx[E + t];
    if ((unsigned)d < (unsigned)N_NODES) atomicAdd(&g_degi[d], 1);
}

// ========================== 2b) scan: offsets + cursors + dinv =============
// Single block, 1024 threads, SCAN_PT elements each (M <= 16384).
__global__ __launch_bounds__(1024)
void scan_kernel(int M)
{
    __shared__ int sums[1024];
    const int t = threadIdx.x;
    const int base = t * SCAN_PT;
    int local[SCAN_PT];
    int s = 0;
#pragma unroll
    for (int j = 0; j < SCAN_PT; ++j) {
        int i = base + j;
        int c = (i < M) ? g_degi[i] : 0;
        local[j] = s;
        s += c;
    }
    sums[t] = s;
    __syncthreads();
    for (int off = 1; off < 1024; off <<= 1) {
        int v = 0;
        if (t >= off) v = sums[t - off];
        __syncthreads();
        if (t >= off) sums[t] += v;
        __syncthreads();
    }
    int excl = (t == 0) ? 0 : sums[t - 1];
#pragma unroll
    for (int j = 0; j < SCAN_PT; ++j) {
        int i = base + j;
        if (i < M) {
            int o = excl + local[j];
            g_off[i]    = o;
            g_cursor[i] = o;
            g_dinv[i]   = rsqrtf(1.0f + (float)g_degi[i]);
        }
    }
    if (t == 1023) g_off[M] = sums[1023];
}

// ========================== 2c) bucket edges by dst ========================
__global__ void bucket_kernel(int E)
{
    int t = blockIdx.x * blockDim.x + threadIdx.x;
    if (t >= E) return;
    int s = g_eidx[t];
    int d = g_eidx[E + t];
    if ((unsigned)s >= (unsigned)N_NODES || (unsigned)d >= (unsigned)N_NODES)
        return;
    int pos = atomicAdd(&g_cursor[d], 1);
    g_esorted[pos] = s;
}

// ========================== 3) gather-reduce (one warp per dst) ============
// enc[d] = h[d]*dinv[d]^2 + sum_{s in bucket(d)} h[s]*dinv[s]*dinv[d] + b_enc
__global__ __launch_bounds__(256)
void gather_reduce_kernel(const float* __restrict__ b_enc, int M)
{
    const int d    = blockIdx.x * 8 + (threadIdx.x >> 5);
    const int lane = threadIdx.x & 31;
    if (d >= M) return;

    const float dd = g_dinv[d];
    const float4* hrow = reinterpret_cast<const float4*>(g_h);

    float4 hv = hrow[(size_t)d * (HID / 4) + lane];
    float sl = dd * dd;
    float4 acc = make_float4(hv.x * sl, hv.y * sl, hv.z * sl, hv.w * sl);

    const int e0 = g_off[d];
    const int e1 = g_off[d + 1];
    for (int e = e0; e < e1; ++e) {
        int s = g_esorted[e];                       // uniform across warp
        float nm = g_dinv[s] * dd;
        float4 v = hrow[(size_t)s * (HID / 4) + lane];
        acc.x = fmaf(v.x, nm, acc.x);
        acc.y = fmaf(v.y, nm, acc.y);
        acc.z = fmaf(v.z, nm, acc.z);
        acc.w = fmaf(v.w, nm, acc.w);
    }
    float4 bb = *reinterpret_cast<const float4*>(b_enc + lane * 4);
    acc.x += bb.x; acc.y += bb.y; acc.z += bb.z; acc.w += bb.w;
    reinterpret_cast<float4*>(g_enc)[(size_t)d * (HID / 4) + lane] = acc;
}

// ========================== 1) encoder GEMM (BM=64, f32x2) =================
// h[M,128] = x[M,512] @ W_enc[512,128].  157 CTAs -> full-chip occupancy.
__global__ __launch_bounds__(256)
void encode_gemm_kernel(const float* __restrict__ A,   // x
                        const float* __restrict__ B,   // W_enc
                        int M)
{
    __shared__ float As[8][64];
    __shared__ float Bs[8][128];

    const int tid = threadIdx.x;
    const int m0  = blockIdx.x * 64;

    const int aRow = tid >> 2;            // 0..63
    const int aCol = (tid & 3) * 2;       // 0,2,4,6
    const int bRow = tid >> 5;            // 0..7
    const int bCol = (tid & 31) * 4;      // 0..124
    const int tr = tid >> 4;              // 0..15 -> rows tr*4..tr*4+3
    const int tc = tid & 15;              // cols tc*8..tc*8+7
    const bool aOK = (m0 + aRow < M);

    unsigned long long acc[4][4];
#pragma unroll
    for (int i = 0; i < 4; ++i)
#pragma unroll
        for (int j = 0; j < 4; ++j) acc[i][j] = 0ull;

    for (int kk = 0; kk < IN_DIM; kk += 8) {
        float2 av = make_float2(0.f, 0.f);
        if (aOK)
            av = *reinterpret_cast<const float2*>(
                     &A[(size_t)(m0 + aRow) * IN_DIM + kk + aCol]);
        As[aCol][aRow]     = av.x;
        As[aCol + 1][aRow] = av.y;
        float4 bv = *reinterpret_cast<const float4*>(
                        &B[(size_t)(kk + bRow) * HID + bCol]);
        *reinterpret_cast<float4*>(&Bs[bRow][bCol]) = bv;
        __syncthreads();

#pragma unroll
        for (int k = 0; k < 8; ++k) {
            float4 a0 = *reinterpret_cast<const float4*>(&As[k][tr * 4]);
            float4 b0 = *reinterpret_cast<const float4*>(&Bs[k][tc * 8]);
            float4 b1 = *reinterpret_cast<const float4*>(&Bs[k][tc * 8 + 4]);
            unsigned long long bp[4];
            asm("mov.b64 %0, {%1, %2};" : "=l"(bp[0]) : "f"(b0.x), "f"(b0.y));
            asm("mov.b64 %0, {%1, %2};" : "=l"(bp[1]) : "f"(b0.z), "f"(b0.w));
            asm("mov.b64 %0, {%1, %2};" : "=l"(bp[2]) : "f"(b1.x), "f"(b1.y));
            asm("mov.b64 %0, {%1, %2};" : "=l"(bp[3]) : "f"(b1.z), "f"(b1.w));
            float a[4] = {a0.x, a0.y, a0.z, a0.w};
#pragma unroll
            for (int i = 0; i < 4; ++i) {
                unsigned long long ap;
                asm("mov.b64 %0, {%1, %2};" : "=l"(ap) : "f"(a[i]), "f"(a[i]));
#pragma unroll
                for (int j = 0; j < 4; ++j)
                    asm("fma.rn.f32x2 %0, %1, %2, %0;"
                        : "+l"(acc[i][j]) : "l"(ap), "l"(bp[j]));
            }
        }
        __syncthreads();
    }

#pragma unroll
    for (int i = 0; i < 4; ++i) {
        int row = m0 + tr * 4 + i;
        if (row >= M) continue;
        float v[8];
#pragma unroll
        for (int j = 0; j < 4; ++j) {
            float lo, hi;
            asm("mov.b64 {%0, %1}, %2;" : "=f"(lo), "=f"(hi) : "l"(acc[i][j]));
            v[2 * j] = lo; v[2 * j + 1] = hi;
        }
        size_t base = (size_t)row * HID + tc * 8;
        *reinterpret_cast<float4*>(&g_h[base]) =
            make_float4(v[0], v[1], v[2], v[3]);
        *reinterpret_cast<float4*>(&g_h[base + 4]) =
            make_float4(v[4], v[5], v[6], v[7]);
    }
}

// ========================== 5) decoder GEMM (R9, proven) ===================
__global__ __launch_bounds__(256, 1)
void decode_kernel(const float* __restrict__ Wd,
                   const float* __restrict__ bd,
                   float* __restrict__ out,
                   int M, int N)
{
    extern __shared__ float dsm[];
    float              (*As)[128] = (float(*)[128])dsm;            // [128][128]
    unsigned long long* Bs2 = (unsigned long long*)(dsm + 128 * 128);

    const int tid = threadIdx.x;
    const int m0  = blockIdx.y * 128;
    const int n0  = blockIdx.x * 128;
    const int tr  = tid >> 4;
    const int tc  = tid & 15;
    const bool fullN = (n0 + 128 <= N);

    {
        const int m   = tid >> 1;
        const int cb  = (tid & 1) * 4;
        const bool ok = (m0 + m < M);
        const float* src = &g_enc[(size_t)(m0 + m) * HID];
#pragma unroll
        for (int kk = 0; kk < 16; ++kk) {
            int col = kk * 8 + cb;
            float4 av = make_float4(0.f, 0.f, 0.f, 0.f);
            if (ok) av = *reinterpret_cast<const float4*>(src + col);
            As[col + 0][m] = av.x;
            As[col + 1][m] = av.y;
            As[col + 2][m] = av.z;
            As[col + 3][m] = av.w;
        }
    }
#pragma unroll
    for (int jj = 0; jj < 16; ++jj) {
        int idx4 = jj * 256 + tid;
        int k    = idx4 >> 5;
        int nq   = idx4 & 31;
        float4 bv;
        if (fullN) {
            bv = *reinterpret_cast<const float4*>(
                     &Wd[(size_t)k * N + n0 + nq * 4]);
        } else {
            float t[4];
#pragma unroll
            for (int i = 0; i < 4; ++i) {
                int c = n0 + nq * 4 + i;
                t[i] = (c < N) ? Wd[(size_t)k * N + c] : 0.f;
            }
            bv = make_float4(t[0], t[1], t[2], t[3]);
        }
        unsigned long long p0, p1;
        asm("mov.b64 %0, {%1, %2};" : "=l"(p0) : "f"(bv.x), "f"(bv.y));
        asm("mov.b64 %0, {%1, %2};" : "=l"(p1) : "f"(bv.z), "f"(bv.w));
        int u0 = k * 64 + ((nq & 1) * 2) * 16 + (nq >> 1);
        Bs2[u0]      = p0;
        Bs2[u0 + 16] = p1;
    }
    __syncthreads();

    unsigned long long acc[8][4];
#pragma unroll
    for (int i = 0; i < 8; ++i)
#pragma unroll
        for (int j = 0; j < 4; ++j) acc[i][j] = 0ull;

#pragma unroll 8
    for (int k = 0; k < 128; ++k) {
        float4 a0 = *reinterpret_cast<const float4*>(&As[k][tr * 8]);
        float4 a1 = *reinterpret_cast<const float4*>(&As[k][tr * 8 + 4]);
        unsigned long long bp[4];
        const unsigned long long* brow = Bs2 + k * 64 + tc;
        bp[0] = brow[0];
        bp[1] = brow[16];
        bp[2] = brow[32];
        bp[3] = brow[48];
        float a[8] = {a0.x, a0.y, a0.z, a0.w, a1.x, a1.y, a1.z, a1.w};
#pragma unroll
        for (int i = 0; i < 8; ++i) {
            unsigned long long ap;
            asm("mov.b64 %0, {%1, %2};" : "=l"(ap) : "f"(a[i]), "f"(a[i]));
#pragma unroll
            for (int j = 0; j < 4; ++j)
                asm("fma.rn.f32x2 %0, %1, %2, %0;"
                    : "+l"(acc[i][j]) : "l"(ap), "l"(bp[j]));
        }
    }

    float bdv[8];
#pragma unroll
    for (int j = 0; j < 8; ++j) {
        int c = n0 + tc * 8 + j;
        bdv[j] = (c < N) ? __ldg(bd + c) : 0.f;
    }
#pragma unroll
    for (int i = 0; i < 8; ++i) {
        int row = m0 + tr * 8 + i;
        if (row >= M) continue;
        float v[8];
#pragma unroll
        for (int j = 0; j < 4; ++j) {
            float lo, hi;
            asm("mov.b64 {%0, %1}, %2;" : "=f"(lo), "=f"(hi) : "l"(acc[i][j]));
            v[2 * j] = lo; v[2 * j + 1] = hi;
        }
#pragma unroll
        for (int j = 0; j < 8; ++j) {
            float t = v[j] + bdv[j];
            v[j] = __fdividef(1.0f, 1.0f + __expf(-t));
        }
        size_t base = (size_t)row * N + n0 + tc * 8;
        if (fullN) {
            *reinterpret_cast<float4*>(&out[base]) =
                make_float4(v[0], v[1], v[2], v[3]);
            *reinterpret_cast<float4*>(&out[base + 4]) =
                make_float4(v[4], v[5], v[6], v[7]);
        } else {
#pragma unroll
            for (int j = 0; j < 8; ++j) {
                int c = n0 + tc * 8 + j;
                if (c < N) out[(size_t)row * N + c] = v[j];
            }
        }
    }
}

#define DEC_SMEM_BYTES (128 * 128 * 4 + 128 * 64 * 8)   // 131072

// ========================== launch =========================================
extern "C" void kernel_launch(void* const* d_in, const int* in_sizes, int n_in,
                              void* d_out, int out_size)
{
    const float* x     = (const float*)d_in[0];
    const void*  ei    = d_in[1];
    const float* W_enc = (const float*)d_in[2];
    const float* b_enc = (const float*)d_in[3];
    const float* W_dec = (const float*)d_in[4];
    const float* b_dec = (const float*)d_in[5];
    float*       out   = (float*)d_out;

    const int M = in_sizes[5];        // 10000
    int E = in_sizes[1] / 2;          // 320000
    if (E > MAX_E) E = MAX_E;

    detect_kernel<<<1, 1>>>(ei);
    convert_edges_kernel<<<(2 * E + 255) / 256, 256>>>(ei, E, M);

    // encoder GEMM (independent of edges; overlaps in-order with small ones)
    encode_gemm_kernel<<<(M + 63) / 64, 256>>>(x, W_enc, M);

    deg_count_kernel<<<(E + 255) / 256, 256>>>(E);
    scan_kernel<<<1, 1024>>>(M);
    bucket_kernel<<<(E + 255) / 256, 256>>>(E);
    gather_reduce_kernel<<<(M + 7) / 8, 256>>>(b_enc, M);

    {
        static int smem_set = 0;
        if (!smem_set) {
            cudaFuncSetAttribute(decode_kernel,
                                 cudaFuncAttributeMaxDynamicSharedMemorySize,
                                 DEC_SMEM_BYTES);
            smem_set = 1;
        }
        dim3 grid((M + 127) / 128, (M + 127) / 128);
        decode_kernel<<<grid, 256, DEC_SMEM_BYTES>>>(W_dec, b_dec, out, M, M);
    }
}

// round 12
// speedup vs baseline: 1.0355x; 1.0099x over previous
#include <cuda_runtime.h>
#include <cuda_bf16.h>
#include <cstdint>

// ---------------------------------------------------------------------------
// GraphAutoencoder (all-SIMT fp32, f32x2-packed FMA pipe):
//   h   = x @ W_enc                                    [N, 128]
//   deg = in-degree(dst) + 1 (self loop); dinv = rsqrt(deg)
//   enc = sum_{e:(s->d)} h[s]*dinv[s]*dinv[d] + h[i]*dinv[i]^2 + b_enc
//   out = sigmoid(enc @ W_dec + b_dec)                 [N, N]
// R12 = best-of: R9 decoder (FFMA2 floor) + R9 atomic scatter (beats sort)
//       + R11 BM=64 encoder (full-chip occupancy) + parallel dtype detect.
// ---------------------------------------------------------------------------

#define N_NODES  10000
#define MAX_E    320000
#define IN_DIM   512
#define HID      128

__device__ __align__(16) float g_h[N_NODES * HID];
__device__ __align__(16) float g_enc[N_NODES * HID];
__device__ float g_deg[N_NODES];
__device__ float g_dinv[N_NODES];
__device__ int   g_eidx[2 * MAX_E];
__device__ int   g_is64;

// ========================== 0) edge dtype handling =========================
// 128 threads sample 128 u64 words; true int64 indices are < 2^31.
__global__ void detect_kernel(const void* __restrict__ e)
{
    const unsigned long long* p = (const unsigned long long*)e;
    int t = threadIdx.x;                               // 0..127
    unsigned long long v = p[(size_t)t * 2499];        // < 320000 words
    unsigned bad = __ballot_sync(0xFFFFFFFFu, v >= (1ull << 31));
    __shared__ int anybad;
    if (threadIdx.x == 0) anybad = 0;
    __syncthreads();
    if ((threadIdx.x & 31) == 0 && bad) atomicOr(&anybad, 1);
    __syncthreads();
    if (threadIdx.x == 0) g_is64 = anybad ? 0 : 1;
}

// convert edges to int32 + initialize degree (self-loop = 1)
__global__ void convert_edges_kernel(const void* __restrict__ e, int E, int M)
{
    int t = blockIdx.x * blockDim.x + threadIdx.x;
    if (t < M) g_deg[t] = 1.0f;
    if (t >= 2 * E) return;
    int v;
    if (g_is64) v = (int)((const long long*)e)[t];
    else        v = ((const int*)e)[t];
    g_eidx[t] = v;
}

// ========================== 2) normalization ===============================
__global__ void deg_count_kernel(int E)
{
    int t = blockIdx.x * blockDim.x + threadIdx.x;
    if (t >= E) return;
    int d = g_eidx[E + t];
    if ((unsigned)d < (unsigned)N_NODES) atomicAdd(&g_deg[d], 1.0f);
}
__global__ void dinv_kernel(int M)
{
    int i = blockIdx.x * blockDim.x + threadIdx.x;
    if (i < M) g_dinv[i] = rsqrtf(g_deg[i]);
}
__global__ void enc_init_kernel(const float* __restrict__ b_enc, int M)
{
    int t = blockIdx.x * blockDim.x + threadIdx.x;
    if (t >= M * HID) return;
    int i = t >> 7;
    int j = t & (HID - 1);
    float di = g_dinv[i];
    g_enc[t] = g_h[t] * di * di + b_enc[j];
}

// ========================== 4) edge scatter (atomic, proven) ===============
__global__ void scatter_kernel(int E)
{
    int warp = (blockIdx.x * blockDim.x + threadIdx.x) >> 5;
    int lane = threadIdx.x & 31;
    if (warp >= E) return;
    int s = g_eidx[warp];
    int d = g_eidx[E + warp];
    if ((unsigned)s >= N_NODES || (unsigned)d >= N_NODES) return;
    float norm = g_dinv[s] * g_dinv[d];
    float4 v = reinterpret_cast<const float4*>(g_h)[(size_t)s * (HID / 4) + lane];
    float* p = g_enc + (size_t)d * HID + lane * 4;
    asm volatile("red.global.add.v4.f32 [%0], {%1, %2, %3, %4};"
                 :: "l"(p), "f"(v.x * norm), "f"(v.y * norm),
                    "f"(v.z * norm), "f"(v.w * norm)
                 : "memory");
}

// ========================== 1) encoder GEMM (BM=64, f32x2) =================
// h[M,128] = x[M,512] @ W_enc[512,128].  157 CTAs -> full-chip occupancy.
__global__ __launch_bounds__(256)
void encode_gemm_kernel(const float* __restrict__ A,   // x
                        const float* __restrict__ B,   // W_enc
                        int M)
{
    __shared__ float As[8][64];
    __shared__ float Bs[8][128];

    const int tid = threadIdx.x;
    const int m0  = blockIdx.x * 64;

    const int aRow = tid >> 2;            // 0..63
    const int aCol = (tid & 3) * 2;       // 0,2,4,6
    const int bRow = tid >> 5;            // 0..7
    const int bCol = (tid & 31) * 4;      // 0..124
    const int tr = tid >> 4;              // 0..15 -> rows tr*4..tr*4+3
    const int tc = tid & 15;              // cols tc*8..tc*8+7
    const bool aOK = (m0 + aRow < M);

    unsigned long long acc[4][4];
#pragma unroll
    for (int i = 0; i < 4; ++i)
#pragma unroll
        for (int j = 0; j < 4; ++j) acc[i][j] = 0ull;

    for (int kk = 0; kk < IN_DIM; kk += 8) {
        float2 av = make_float2(0.f, 0.f);
        if (aOK)
            av = *reinterpret_cast<const float2*>(
                     &A[(size_t)(m0 + aRow) * IN_DIM + kk + aCol]);
        As[aCol][aRow]     = av.x;
        As[aCol + 1][aRow] = av.y;
        float4 bv = *reinterpret_cast<const float4*>(
                        &B[(size_t)(kk + bRow) * HID + bCol]);
        *reinterpret_cast<float4*>(&Bs[bRow][bCol]) = bv;
        __syncthreads();

#pragma unroll
        for (int k = 0; k < 8; ++k) {
            float4 a0 = *reinterpret_cast<const float4*>(&As[k][tr * 4]);
            float4 b0 = *reinterpret_cast<const float4*>(&Bs[k][tc * 8]);
            float4 b1 = *reinterpret_cast<const float4*>(&Bs[k][tc * 8 + 4]);
            unsigned long long bp[4];
            asm("mov.b64 %0, {%1, %2};" : "=l"(bp[0]) : "f"(b0.x), "f"(b0.y));
            asm("mov.b64 %0, {%1, %2};" : "=l"(bp[1]) : "f"(b0.z), "f"(b0.w));
            asm("mov.b64 %0, {%1, %2};" : "=l"(bp[2]) : "f"(b1.x), "f"(b1.y));
            asm("mov.b64 %0, {%1, %2};" : "=l"(bp[3]) : "f"(b1.z), "f"(b1.w));
            float a[4] = {a0.x, a0.y, a0.z, a0.w};
#pragma unroll
            for (int i = 0; i < 4; ++i) {
                unsigned long long ap;
                asm("mov.b64 %0, {%1, %2};" : "=l"(ap) : "f"(a[i]), "f"(a[i]));
#pragma unroll
                for (int j = 0; j < 4; ++j)
                    asm("fma.rn.f32x2 %0, %1, %2, %0;"
                        : "+l"(acc[i][j]) : "l"(ap), "l"(bp[j]));
            }
        }
        __syncthreads();
    }

#pragma unroll
    for (int i = 0; i < 4; ++i) {
        int row = m0 + tr * 4 + i;
        if (row >= M) continue;
        float v[8];
#pragma unroll
        for (int j = 0; j < 4; ++j) {
            float lo, hi;
            asm("mov.b64 {%0, %1}, %2;" : "=f"(lo), "=f"(hi) : "l"(acc[i][j]));
            v[2 * j] = lo; v[2 * j + 1] = hi;
        }
        size_t base = (size_t)row * HID + tc * 8;
        *reinterpret_cast<float4*>(&g_h[base]) =
            make_float4(v[0], v[1], v[2], v[3]);
        *reinterpret_cast<float4*>(&g_h[base + 4]) =
            make_float4(v[4], v[5], v[6], v[7]);
    }
}

// ========================== 5) decoder GEMM (R9, proven) ===================
__global__ __launch_bounds__(256, 1)
void decode_kernel(const float* __restrict__ Wd,
                   const float* __restrict__ bd,
                   float* __restrict__ out,
                   int M, int N)
{
    extern __shared__ float dsm[];
    float              (*As)[128] = (float(*)[128])dsm;            // [128][128]
    unsigned long long* Bs2 = (unsigned long long*)(dsm + 128 * 128);

    const int tid = threadIdx.x;
    const int m0  = blockIdx.y * 128;
    const int n0  = blockIdx.x * 128;
    const int tr  = tid >> 4;
    const int tc  = tid & 15;
    const bool fullN = (n0 + 128 <= N);

    {
        const int m   = tid >> 1;
        const int cb  = (tid & 1) * 4;
        const bool ok = (m0 + m < M);
        const float* src = &g_enc[(size_t)(m0 + m) * HID];
#pragma unroll
        for (int kk = 0; kk < 16; ++kk) {
            int col = kk * 8 + cb;
            float4 av = make_float4(0.f, 0.f, 0.f, 0.f);
            if (ok) av = *reinterpret_cast<const float4*>(src + col);
            As[col + 0][m] = av.x;
            As[col + 1][m] = av.y;
            As[col + 2][m] = av.z;
            As[col + 3][m] = av.w;
        }
    }
#pragma unroll
    for (int jj = 0; jj < 16; ++jj) {
        int idx4 = jj * 256 + tid;
        int k    = idx4 >> 5;
        int nq   = idx4 & 31;
        float4 bv;
        if (fullN) {
            bv = *reinterpret_cast<const float4*>(
                     &Wd[(size_t)k * N + n0 + nq * 4]);
        } else {
            float t[4];
#pragma unroll
            for (int i = 0; i < 4; ++i) {
                int c = n0 + nq * 4 + i;
                t[i] = (c < N) ? Wd[(size_t)k * N + c] : 0.f;
            }
            bv = make_float4(t[0], t[1], t[2], t[3]);
        }
        unsigned long long p0, p1;
        asm("mov.b64 %0, {%1, %2};" : "=l"(p0) : "f"(bv.x), "f"(bv.y));
        asm("mov.b64 %0, {%1, %2};" : "=l"(p1) : "f"(bv.z), "f"(bv.w));
        int u0 = k * 64 + ((nq & 1) * 2) * 16 + (nq >> 1);
        Bs2[u0]      = p0;
        Bs2[u0 + 16] = p1;
    }
    __syncthreads();

    unsigned long long acc[8][4];
#pragma unroll
    for (int i = 0; i < 8; ++i)
#pragma unroll
        for (int j = 0; j < 4; ++j) acc[i][j] = 0ull;

#pragma unroll 8
    for (int k = 0; k < 128; ++k) {
        float4 a0 = *reinterpret_cast<const float4*>(&As[k][tr * 8]);
        float4 a1 = *reinterpret_cast<const float4*>(&As[k][tr * 8 + 4]);
        unsigned long long bp[4];
        const unsigned long long* brow = Bs2 + k * 64 + tc;
        bp[0] = brow[0];
        bp[1] = brow[16];
        bp[2] = brow[32];
        bp[3] = brow[48];
        float a[8] = {a0.x, a0.y, a0.z, a0.w, a1.x, a1.y, a1.z, a1.w};
#pragma unroll
        for (int i = 0; i < 8; ++i) {
            unsigned long long ap;
            asm("mov.b64 %0, {%1, %2};" : "=l"(ap) : "f"(a[i]), "f"(a[i]));
#pragma unroll
            for (int j = 0; j < 4; ++j)
                asm("fma.rn.f32x2 %0, %1, %2, %0;"
                    : "+l"(acc[i][j]) : "l"(ap), "l"(bp[j]));
        }
    }

    float bdv[8];
#pragma unroll
    for (int j = 0; j < 8; ++j) {
        int c = n0 + tc * 8 + j;
        bdv[j] = (c < N) ? __ldg(bd + c) : 0.f;
    }
#pragma unroll
    for (int i = 0; i < 8; ++i) {
        int row = m0 + tr * 8 + i;
        if (row >= M) continue;
        float v[8];
#pragma unroll
        for (int j = 0; j < 4; ++j) {
            float lo, hi;
            asm("mov.b64 {%0, %1}, %2;" : "=f"(lo), "=f"(hi) : "l"(acc[i][j]));
            v[2 * j] = lo; v[2 * j + 1] = hi;
        }
#pragma unroll
        for (int j = 0; j < 8; ++j) {
            float t = v[j] + bdv[j];
            v[j] = __fdividef(1.0f, 1.0f + __expf(-t));
        }
        size_t base = (size_t)row * N + n0 + tc * 8;
        if (fullN) {
            *reinterpret_cast<float4*>(&out[base]) =
                make_float4(v[0], v[1], v[2], v[3]);
            *reinterpret_cast<float4*>(&out[base + 4]) =
                make_float4(v[4], v[5], v[6], v[7]);
        } else {
#pragma unroll
            for (int j = 0; j < 8; ++j) {
                int c = n0 + tc * 8 + j;
                if (c < N) out[(size_t)row * N + c] = v[j];
            }
        }
    }
}

#define DEC_SMEM_BYTES (128 * 128 * 4 + 128 * 64 * 8)   // 131072

// ========================== launch =========================================
extern "C" void kernel_launch(void* const* d_in, const int* in_sizes, int n_in,
                              void* d_out, int out_size)
{
    const float* x     = (const float*)d_in[0];
    const void*  ei    = d_in[1];
    const float* W_enc = (const float*)d_in[2];
    const float* b_enc = (const float*)d_in[3];
    const float* W_dec = (const float*)d_in[4];
    const float* b_dec = (const float*)d_in[5];
    float*       out   = (float*)d_out;

    const int M = in_sizes[5];        // 10000
    int E = in_sizes[1] / 2;          // 320000
    if (E > MAX_E) E = MAX_E;

    detect_kernel<<<1, 128>>>(ei);
    convert_edges_kernel<<<(2 * E + 255) / 256, 256>>>(ei, E, M);

    // encoder GEMM (BM=64: 157 CTAs, full-chip)
    encode_gemm_kernel<<<(M + 63) / 64, 256>>>(x, W_enc, M);

    deg_count_kernel<<<(E + 255) / 256, 256>>>(E);
    dinv_kernel     <<<(M + 255) / 256, 256>>>(M);
    enc_init_kernel <<<(M * HID + 255) / 256, 256>>>(b_enc, M);
    {
        int wpb = 256 / 32;
        scatter_kernel<<<(E + wpb - 1) / wpb, 256>>>(E);
    }
    {
        static int smem_set = 0;
        if (!smem_set) {
            cudaFuncSetAttribute(decode_kernel,
                                 cudaFuncAttributeMaxDynamicSharedMemorySize,
                                 DEC_SMEM_BYTES);
            smem_set = 1;
        }
        dim3 grid((M + 127) / 128, (M + 127) / 128);
        decode_kernel<<<grid, 256, DEC_SMEM_BYTES>>>(W_dec, b_dec, out, M, M);
    }
}

// round 13
// speedup vs baseline: 1.0715x; 1.0348x over previous
#include <cuda_runtime.h>
#include <cuda_bf16.h>
#include <cstdint>

// ---------------------------------------------------------------------------
// GraphAutoencoder (all-SIMT fp32, f32x2-packed FMA pipe):
//   h   = x @ W_enc                                    [N, 128]
//   deg = in-degree(dst) + 1 (self loop); dinv = rsqrt(deg)
//   enc = sum_{e:(s->d)} h[s]*dinv[s]*dinv[d] + h[i]*dinv[i]^2 + b_enc
//   out = sigmoid(enc @ W_dec + b_dec)                 [N, N]
// R13 = R9 (proven best: BM=128 encoder, atomic scatter, FFMA2 decoder at
// its rt=3 banking floor) + kernel fusion of the small passes:
//   detect absorbs deg-init; convert absorbs deg_count.  7 launches total.
// ---------------------------------------------------------------------------

#define N_NODES  10000
#define MAX_E    320000
#define IN_DIM   512
#define HID      128

__device__ __align__(16) float g_h[N_NODES * HID];
__device__ __align__(16) float g_enc[N_NODES * HID];
__device__ float g_deg[N_NODES];
__device__ float g_dinv[N_NODES];
__device__ int   g_eidx[2 * MAX_E];
__device__ int   g_is64;

// ========================== 0) dtype detect + deg init =====================
// 128 threads: sample 128 u64 words (int64 node ids are < 2^31) and
// initialize g_deg to 1.0 (self loop).
__global__ void detect_kernel(const void* __restrict__ e, int M)
{
    const unsigned long long* p = (const unsigned long long*)e;
    int t = threadIdx.x;                               // 0..127
    unsigned long long v = p[(size_t)t * 2499];        // < 320000 words
    unsigned bad = __ballot_sync(0xFFFFFFFFu, v >= (1ull << 31));
    __shared__ int anybad;
    if (t == 0) anybad = 0;
    __syncthreads();
    if ((t & 31) == 0 && bad) atomicOr(&anybad, 1);
    __syncthreads();
    if (t == 0) g_is64 = anybad ? 0 : 1;
    for (int i = t; i < M; i += 128) g_deg[i] = 1.0f;
}

// ========================== 0b) convert + degree count =====================
// Converts edge_index to canonical int32 and counts dst in-degrees in the
// same pass (detect_kernel completed deg init on the in-order stream).
__global__ void convert_edges_kernel(const void* __restrict__ e, int E)
{
    int t = blockIdx.x * blockDim.x + threadIdx.x;
    if (t >= 2 * E) return;
    int v;
    if (g_is64) v = (int)((const long long*)e)[t];
    else        v = ((const int*)e)[t];
    g_eidx[t] = v;
    if (t >= E && (unsigned)v < (unsigned)N_NODES)
        atomicAdd(&g_deg[v], 1.0f);                    // dst in-degree
}

// ========================== 2) normalization ===============================
__global__ void dinv_kernel(int M)
{
    int i = blockIdx.x * blockDim.x + threadIdx.x;
    if (i < M) g_dinv[i] = rsqrtf(g_deg[i]);
}
__global__ void enc_init_kernel(const float* __restrict__ b_enc, int M)
{
    int t = blockIdx.x * blockDim.x + threadIdx.x;
    if (t >= M * HID) return;
    int i = t >> 7;
    int j = t & (HID - 1);
    float di = g_dinv[i];
    g_enc[t] = g_h[t] * di * di + b_enc[j];
}

// ========================== 4) edge scatter (atomic, proven) ===============
__global__ void scatter_kernel(int E)
{
    int warp = (blockIdx.x * blockDim.x + threadIdx.x) >> 5;
    int lane = threadIdx.x & 31;
    if (warp >= E) return;
    int s = g_eidx[warp];
    int d = g_eidx[E + warp];
    if ((unsigned)s >= N_NODES || (unsigned)d >= N_NODES) return;
    float norm = g_dinv[s] * g_dinv[d];
    float4 v = reinterpret_cast<const float4*>(g_h)[(size_t)s * (HID / 4) + lane];
    float* p = g_enc + (size_t)d * HID + lane * 4;
    asm volatile("red.global.add.v4.f32 [%0], {%1, %2, %3, %4};"
                 :: "l"(p), "f"(v.x * norm), "f"(v.y * norm),
                    "f"(v.z * norm), "f"(v.w * norm)
                 : "memory");
}

// ========================== 1) encoder GEMM (R9: BM=128, f32x2) ============
#define EN_BK 8
__global__ __launch_bounds__(256)
void encode_gemm_kernel(const float* __restrict__ A,   // x
                        const float* __restrict__ B,   // W_enc
                        int M)
{
    __shared__ float As[EN_BK][128];
    __shared__ float Bs[EN_BK][128];

    const int tid = threadIdx.x;
    const int m0  = blockIdx.y * 128;

    const int aRow = tid >> 1;
    const int aCol = (tid & 1) * 4;
    const int bRow = tid >> 5;
    const int bCol = (tid & 31) * 4;
    const int tr = tid >> 4;
    const int tc = tid & 15;
    const bool aOK = (m0 + aRow < M);

    unsigned long long acc[8][4];
#pragma unroll
    for (int i = 0; i < 8; ++i)
#pragma unroll
        for (int j = 0; j < 4; ++j) acc[i][j] = 0ull;

    for (int kk = 0; kk < IN_DIM; kk += EN_BK) {
        float4 av = make_float4(0.f, 0.f, 0.f, 0.f);
        if (aOK)
            av = *reinterpret_cast<const float4*>(
                     &A[(size_t)(m0 + aRow) * IN_DIM + kk + aCol]);
        As[aCol + 0][aRow] = av.x;
        As[aCol + 1][aRow] = av.y;
        As[aCol + 2][aRow] = av.z;
        As[aCol + 3][aRow] = av.w;
        float4 bv = *reinterpret_cast<const float4*>(
                        &B[(size_t)(kk + bRow) * HID + bCol]);
        *reinterpret_cast<float4*>(&Bs[bRow][bCol]) = bv;
        __syncthreads();

#pragma unroll
        for (int k = 0; k < EN_BK; ++k) {
            float4 a0 = *reinterpret_cast<const float4*>(&As[k][tr * 8]);
            float4 a1 = *reinterpret_cast<const float4*>(&As[k][tr * 8 + 4]);
            float4 b0 = *reinterpret_cast<const float4*>(&Bs[k][tc * 8]);
            float4 b1 = *reinterpret_cast<const float4*>(&Bs[k][tc * 8 + 4]);
            unsigned long long bp[4];
            asm("mov.b64 %0, {%1, %2};" : "=l"(bp[0]) : "f"(b0.x), "f"(b0.y));
            asm("mov.b64 %0, {%1, %2};" : "=l"(bp[1]) : "f"(b0.z), "f"(b0.w));
            asm("mov.b64 %0, {%1, %2};" : "=l"(bp[2]) : "f"(b1.x), "f"(b1.y));
            asm("mov.b64 %0, {%1, %2};" : "=l"(bp[3]) : "f"(b1.z), "f"(b1.w));
            float a[8] = {a0.x, a0.y, a0.z, a0.w, a1.x, a1.y, a1.z, a1.w};
#pragma unroll
            for (int i = 0; i < 8; ++i) {
                unsigned long long ap;
                asm("mov.b64 %0, {%1, %2};" : "=l"(ap) : "f"(a[i]), "f"(a[i]));
#pragma unroll
                for (int j = 0; j < 4; ++j)
                    asm("fma.rn.f32x2 %0, %1, %2, %0;"
                        : "+l"(acc[i][j]) : "l"(ap), "l"(bp[j]));
            }
        }
        __syncthreads();
    }

#pragma unroll
    for (int i = 0; i < 8; ++i) {
        int row = m0 + tr * 8 + i;
        if (row >= M) continue;
        float v[8];
#pragma unroll
        for (int j = 0; j < 4; ++j) {
            float lo, hi;
            asm("mov.b64 {%0, %1}, %2;" : "=f"(lo), "=f"(hi) : "l"(acc[i][j]));
            v[2 * j] = lo; v[2 * j + 1] = hi;
        }
        size_t base = (size_t)row * HID + tc * 8;
        *reinterpret_cast<float4*>(&g_h[base]) =
            make_float4(v[0], v[1], v[2], v[3]);
        *reinterpret_cast<float4*>(&g_h[base + 4]) =
            make_float4(v[4], v[5], v[6], v[7]);
    }
}

// ========================== 5) decoder GEMM (R9, proven) ===================
__global__ __launch_bounds__(256, 1)
void decode_kernel(const float* __restrict__ Wd,
                   const float* __restrict__ bd,
                   float* __restrict__ out,
                   int M, int N)
{
    extern __shared__ float dsm[];
    float              (*As)[128] = (float(*)[128])dsm;            // [128][128]
    unsigned long long* Bs2 = (unsigned long long*)(dsm + 128 * 128);

    const int tid = threadIdx.x;
    const int m0  = blockIdx.y * 128;
    const int n0  = blockIdx.x * 128;
    const int tr  = tid >> 4;
    const int tc  = tid & 15;
    const bool fullN = (n0 + 128 <= N);

    {
        const int m   = tid >> 1;
        const int cb  = (tid & 1) * 4;
        const bool ok = (m0 + m < M);
        const float* src = &g_enc[(size_t)(m0 + m) * HID];
#pragma unroll
        for (int kk = 0; kk < 16; ++kk) {
            int col = kk * 8 + cb;
            float4 av = make_float4(0.f, 0.f, 0.f, 0.f);
            if (ok) av = *reinterpret_cast<const float4*>(src + col);
            As[col + 0][m] = av.x;
            As[col + 1][m] = av.y;
            As[col + 2][m] = av.z;
            As[col + 3][m] = av.w;
        }
    }
#pragma unroll
    for (int jj = 0; jj < 16; ++jj) {
        int idx4 = jj * 256 + tid;
        int k    = idx4 >> 5;
        int nq   = idx4 & 31;
        float4 bv;
        if (fullN) {
            bv = *reinterpret_cast<const float4*>(
                     &Wd[(size_t)k * N + n0 + nq * 4]);
        } else {
            float t[4];
#pragma unroll
            for (int i = 0; i < 4; ++i) {
                int c = n0 + nq * 4 + i;
                t[i] = (c < N) ? Wd[(size_t)k * N + c] : 0.f;
            }
            bv = make_float4(t[0], t[1], t[2], t[3]);
        }
        unsigned long long p0, p1;
        asm("mov.b64 %0, {%1, %2};" : "=l"(p0) : "f"(bv.x), "f"(bv.y));
        asm("mov.b64 %0, {%1, %2};" : "=l"(p1) : "f"(bv.z), "f"(bv.w));
        int u0 = k * 64 + ((nq & 1) * 2) * 16 + (nq >> 1);
        Bs2[u0]      = p0;
        Bs2[u0 + 16] = p1;
    }
    __syncthreads();

    unsigned long long acc[8][4];
#pragma unroll
    for (int i = 0; i < 8; ++i)
#pragma unroll
        for (int j = 0; j < 4; ++j) acc[i][j] = 0ull;

#pragma unroll 8
    for (int k = 0; k < 128; ++k) {
        float4 a0 = *reinterpret_cast<const float4*>(&As[k][tr * 8]);
        float4 a1 = *reinterpret_cast<const float4*>(&As[k][tr * 8 + 4]);
        unsigned long long bp[4];
        const unsigned long long* brow = Bs2 + k * 64 + tc;
        bp[0] = brow[0];
        bp[1] = brow[16];
        bp[2] = brow[32];
        bp[3] = brow[48];
        float a[8] = {a0.x, a0.y, a0.z, a0.w, a1.x, a1.y, a1.z, a1.w};
#pragma unroll
        for (int i = 0; i < 8; ++i) {
            unsigned long long ap;
            asm("mov.b64 %0, {%1, %2};" : "=l"(ap) : "f"(a[i]), "f"(a[i]));
#pragma unroll
            for (int j = 0; j < 4; ++j)
                asm("fma.rn.f32x2 %0, %1, %2, %0;"
                    : "+l"(acc[i][j]) : "l"(ap), "l"(bp[j]));
        }
    }

    float bdv[8];
#pragma unroll
    for (int j = 0; j < 8; ++j) {
        int c = n0 + tc * 8 + j;
        bdv[j] = (c < N) ? __ldg(bd + c) : 0.f;
    }
#pragma unroll
    for (int i = 0; i < 8; ++i) {
        int row = m0 + tr * 8 + i;
        if (row >= M) continue;
        float v[8];
#pragma unroll
        for (int j = 0; j < 4; ++j) {
            float lo, hi;
            asm("mov.b64 {%0, %1}, %2;" : "=f"(lo), "=f"(hi) : "l"(acc[i][j]));
            v[2 * j] = lo; v[2 * j + 1] = hi;
        }
#pragma unroll
        for (int j = 0; j < 8; ++j) {
            float t = v[j] + bdv[j];
            v[j] = __fdividef(1.0f, 1.0f + __expf(-t));
        }
        size_t base = (size_t)row * N + n0 + tc * 8;
        if (fullN) {
            *reinterpret_cast<float4*>(&out[base]) =
                make_float4(v[0], v[1], v[2], v[3]);
            *reinterpret_cast<float4*>(&out[base + 4]) =
                make_float4(v[4], v[5], v[6], v[7]);
        } else {
#pragma unroll
            for (int j = 0; j < 8; ++j) {
                int c = n0 + tc * 8 + j;
                if (c < N) out[(size_t)row * N + c] = v[j];
            }
        }
    }
}

#define DEC_SMEM_BYTES (128 * 128 * 4 + 128 * 64 * 8)   // 131072

// ========================== launch =========================================
extern "C" void kernel_launch(void* const* d_in, const int* in_sizes, int n_in,
                              void* d_out, int out_size)
{
    const float* x     = (const float*)d_in[0];
    const void*  ei    = d_in[1];
    const float* W_enc = (const float*)d_in[2];
    const float* b_enc = (const float*)d_in[3];
    const float* W_dec = (const float*)d_in[4];
    const float* b_dec = (const float*)d_in[5];
    float*       out   = (float*)d_out;

    const int M = in_sizes[5];        // 10000
    int E = in_sizes[1] / 2;          // 320000
    if (E > MAX_E) E = MAX_E;

    // dtype detect + deg init (one small block)
    detect_kernel<<<1, 128>>>(ei, M);
    // convert + dst degree count (single edge pass)
    convert_edges_kernel<<<(2 * E + 255) / 256, 256>>>(ei, E);

    // encoder GEMM (R9: BM=128, 79 CTAs — measured best)
    {
        dim3 grid(1, (M + 127) / 128);
        encode_gemm_kernel<<<grid, 256>>>(x, W_enc, M);
    }
    dinv_kernel     <<<(M + 255) / 256, 256>>>(M);
    enc_init_kernel <<<(M * HID + 255) / 256, 256>>>(b_enc, M);
    {
        int wpb = 256 / 32;
        scatter_kernel<<<(E + wpb - 1) / wpb, 256>>>(E);
    }
    {
        static int smem_set = 0;
        if (!smem_set) {
            cudaFuncSetAttribute(decode_kernel,
                                 cudaFuncAttributeMaxDynamicSharedMemorySize,
                                 DEC_SMEM_BYTES);
            smem_set = 1;
        }
        dim3 grid((M + 127) / 128, (M + 127) / 128);
        decode_kernel<<<grid, 256, DEC_SMEM_BYTES>>>(W_dec, b_dec, out, M, M);
    }
}

// round 14
// speedup vs baseline: 1.0866x; 1.0140x over previous
#include <cuda_runtime.h>
#include <cuda_bf16.h>
#include <cstdint>

// ---------------------------------------------------------------------------
// GraphAutoencoder (all-SIMT fp32, f32x2-packed FMA pipe):
//   h   = x @ W_enc                                    [N, 128]
//   deg = in-degree(dst) + 1 (self loop); dinv = rsqrt(deg)
//   enc = sum_{e:(s->d)} h[s]*dinv[s]*dinv[d] + h[i]*dinv[i]^2 + b_enc
//   out = sigmoid(enc @ W_dec + b_dec)                 [N, N]
// R14 = R13 + split-K=2 encoder (158 CTAs, full-chip; partials combined in
// enc_init) + dinv folded into enc_init.  6 launches total.
// Decoder unchanged: FFMA2 rt=3 banking floor (proven R9 config).
// ---------------------------------------------------------------------------

#define N_NODES  10000
#define MAX_E    320000
#define IN_DIM   512
#define HID      128

__device__ __align__(16) float g_h [N_NODES * HID];   // K-half 0 partial -> combined
__device__ __align__(16) float g_h2[N_NODES * HID];   // K-half 1 partial
__device__ __align__(16) float g_enc[N_NODES * HID];
__device__ float g_deg[N_NODES];
__device__ float g_dinv[N_NODES];
__device__ int   g_eidx[2 * MAX_E];
__device__ int   g_is64;

// ========================== 0) dtype detect + deg init =====================
__global__ void detect_kernel(const void* __restrict__ e, int M)
{
    const unsigned long long* p = (const unsigned long long*)e;
    int t = threadIdx.x;                               // 0..127
    unsigned long long v = p[(size_t)t * 2499];        // < 320000 words
    unsigned bad = __ballot_sync(0xFFFFFFFFu, v >= (1ull << 31));
    __shared__ int anybad;
    if (t == 0) anybad = 0;
    __syncthreads();
    if ((t & 31) == 0 && bad) atomicOr(&anybad, 1);
    __syncthreads();
    if (t == 0) g_is64 = anybad ? 0 : 1;
    for (int i = t; i < M; i += 128) g_deg[i] = 1.0f;  // self loop
}

// ========================== 0b) convert + degree count =====================
__global__ void convert_edges_kernel(const void* __restrict__ e, int E)
{
    int t = blockIdx.x * blockDim.x + threadIdx.x;
    if (t >= 2 * E) return;
    int v;
    if (g_is64) v = (int)((const long long*)e)[t];
    else        v = ((const int*)e)[t];
    g_eidx[t] = v;
    if (t >= E && (unsigned)v < (unsigned)N_NODES)
        atomicAdd(&g_deg[v], 1.0f);                    // dst in-degree
}

// ========================== 1) encoder GEMM (split-K=2, BM=128) ============
// h_partial[M,128] = x[M, kx*256 : kx*256+256] @ W_enc[same rows, 128]
// grid = (2, ceil(M/128)); kx selects K half and output buffer.
#define EN_BK 8
__global__ __launch_bounds__(256)
void encode_gemm_kernel(const float* __restrict__ A,   // x
                        const float* __restrict__ B,   // W_enc
                        int M)
{
    __shared__ float As[EN_BK][128];
    __shared__ float Bs[EN_BK][128];

    const int tid = threadIdx.x;
    const int m0  = blockIdx.y * 128;
    const int k0  = blockIdx.x * (IN_DIM / 2);
    float* __restrict__ dst = (blockIdx.x == 0) ? g_h : g_h2;

    const int aRow = tid >> 1;
    const int aCol = (tid & 1) * 4;
    const int bRow = tid >> 5;
    const int bCol = (tid & 31) * 4;
    const int tr = tid >> 4;
    const int tc = tid & 15;
    const bool aOK = (m0 + aRow < M);

    unsigned long long acc[8][4];
#pragma unroll
    for (int i = 0; i < 8; ++i)
#pragma unroll
        for (int j = 0; j < 4; ++j) acc[i][j] = 0ull;

    for (int kk = k0; kk < k0 + IN_DIM / 2; kk += EN_BK) {
        float4 av = make_float4(0.f, 0.f, 0.f, 0.f);
        if (aOK)
            av = *reinterpret_cast<const float4*>(
                     &A[(size_t)(m0 + aRow) * IN_DIM + kk + aCol]);
        As[aCol + 0][aRow] = av.x;
        As[aCol + 1][aRow] = av.y;
        As[aCol + 2][aRow] = av.z;
        As[aCol + 3][aRow] = av.w;
        float4 bv = *reinterpret_cast<const float4*>(
                        &B[(size_t)(kk + bRow) * HID + bCol]);
        *reinterpret_cast<float4*>(&Bs[bRow][bCol]) = bv;
        __syncthreads();

#pragma unroll
        for (int k = 0; k < EN_BK; ++k) {
            float4 a0 = *reinterpret_cast<const float4*>(&As[k][tr * 8]);
            float4 a1 = *reinterpret_cast<const float4*>(&As[k][tr * 8 + 4]);
            float4 b0 = *reinterpret_cast<const float4*>(&Bs[k][tc * 8]);
            float4 b1 = *reinterpret_cast<const float4*>(&Bs[k][tc * 8 + 4]);
            unsigned long long bp[4];
            asm("mov.b64 %0, {%1, %2};" : "=l"(bp[0]) : "f"(b0.x), "f"(b0.y));
            asm("mov.b64 %0, {%1, %2};" : "=l"(bp[1]) : "f"(b0.z), "f"(b0.w));
            asm("mov.b64 %0, {%1, %2};" : "=l"(bp[2]) : "f"(b1.x), "f"(b1.y));
            asm("mov.b64 %0, {%1, %2};" : "=l"(bp[3]) : "f"(b1.z), "f"(b1.w));
            float a[8] = {a0.x, a0.y, a0.z, a0.w, a1.x, a1.y, a1.z, a1.w};
#pragma unroll
            for (int i = 0; i < 8; ++i) {
                unsigned long long ap;
                asm("mov.b64 %0, {%1, %2};" : "=l"(ap) : "f"(a[i]), "f"(a[i]));
#pragma unroll
                for (int j = 0; j < 4; ++j)
                    asm("fma.rn.f32x2 %0, %1, %2, %0;"
                        : "+l"(acc[i][j]) : "l"(ap), "l"(bp[j]));
            }
        }
        __syncthreads();
    }

#pragma unroll
    for (int i = 0; i < 8; ++i) {
        int row = m0 + tr * 8 + i;
        if (row >= M) continue;
        float v[8];
#pragma unroll
        for (int j = 0; j < 4; ++j) {
            float lo, hi;
            asm("mov.b64 {%0, %1}, %2;" : "=f"(lo), "=f"(hi) : "l"(acc[i][j]));
            v[2 * j] = lo; v[2 * j + 1] = hi;
        }
        size_t base = (size_t)row * HID + tc * 8;
        *reinterpret_cast<float4*>(&dst[base]) =
            make_float4(v[0], v[1], v[2], v[3]);
        *reinterpret_cast<float4*>(&dst[base + 4]) =
            make_float4(v[4], v[5], v[6], v[7]);
    }
}

// ========================== 3) enc init: combine + dinv + self-loop ========
// g_h  <- g_h + g_h2 (split-K combine, persisted for scatter's gather)
// dinv <- rsqrt(deg)  (lane j==0 persists for scatter)
// enc  <- h*dinv^2 + b_enc
__global__ void enc_init_kernel(const float* __restrict__ b_enc, int M)
{
    int t = blockIdx.x * blockDim.x + threadIdx.x;
    if (t >= M * HID) return;
    int i = t >> 7;
    int j = t & (HID - 1);
    float sum = g_h[t] + g_h2[t];
    g_h[t] = sum;
    float di = rsqrtf(g_deg[i]);
    if (j == 0) g_dinv[i] = di;
    g_enc[t] = sum * di * di + b_enc[j];
}

// ========================== 4) edge scatter (atomic, proven) ===============
__global__ void scatter_kernel(int E)
{
    int warp = (blockIdx.x * blockDim.x + threadIdx.x) >> 5;
    int lane = threadIdx.x & 31;
    if (warp >= E) return;
    int s = g_eidx[warp];
    int d = g_eidx[E + warp];
    if ((unsigned)s >= N_NODES || (unsigned)d >= N_NODES) return;
    float norm = g_dinv[s] * g_dinv[d];
    float4 v = reinterpret_cast<const float4*>(g_h)[(size_t)s * (HID / 4) + lane];
    float* p = g_enc + (size_t)d * HID + lane * 4;
    asm volatile("red.global.add.v4.f32 [%0], {%1, %2, %3, %4};"
                 :: "l"(p), "f"(v.x * norm), "f"(v.y * norm),
                    "f"(v.z * norm), "f"(v.w * norm)
                 : "memory");
}

// ========================== 5) decoder GEMM (R9, proven) ===================
__global__ __launch_bounds__(256, 1)
void decode_kernel(const float* __restrict__ Wd,
                   const float* __restrict__ bd,
                   float* __restrict__ out,
                   int M, int N)
{
    extern __shared__ float dsm[];
    float              (*As)[128] = (float(*)[128])dsm;            // [128][128]
    unsigned long long* Bs2 = (unsigned long long*)(dsm + 128 * 128);

    const int tid = threadIdx.x;
    const int m0  = blockIdx.y * 128;
    const int n0  = blockIdx.x * 128;
    const int tr  = tid >> 4;
    const int tc  = tid & 15;
    const bool fullN = (n0 + 128 <= N);

    {
        const int m   = tid >> 1;
        const int cb  = (tid & 1) * 4;
        const bool ok = (m0 + m < M);
        const float* src = &g_enc[(size_t)(m0 + m) * HID];
#pragma unroll
        for (int kk = 0; kk < 16; ++kk) {
            int col = kk * 8 + cb;
            float4 av = make_float4(0.f, 0.f, 0.f, 0.f);
            if (ok) av = *reinterpret_cast<const float4*>(src + col);
            As[col + 0][m] = av.x;
            As[col + 1][m] = av.y;
            As[col + 2][m] = av.z;
            As[col + 3][m] = av.w;
        }
    }
#pragma unroll
    for (int jj = 0; jj < 16; ++jj) {
        int idx4 = jj * 256 + tid;
        int k    = idx4 >> 5;
        int nq   = idx4 & 31;
        float4 bv;
        if (fullN) {
            bv = *reinterpret_cast<const float4*>(
                     &Wd[(size_t)k * N + n0 + nq * 4]);
        } else {
            float t[4];
#pragma unroll
            for (int i = 0; i < 4; ++i) {
                int c = n0 + nq * 4 + i;
                t[i] = (c < N) ? Wd[(size_t)k * N + c] : 0.f;
            }
            bv = make_float4(t[0], t[1], t[2], t[3]);
        }
        unsigned long long p0, p1;
        asm("mov.b64 %0, {%1, %2};" : "=l"(p0) : "f"(bv.x), "f"(bv.y));
        asm("mov.b64 %0, {%1, %2};" : "=l"(p1) : "f"(bv.z), "f"(bv.w));
        int u0 = k * 64 + ((nq & 1) * 2) * 16 + (nq >> 1);
        Bs2[u0]      = p0;
        Bs2[u0 + 16] = p1;
    }
    __syncthreads();

    unsigned long long acc[8][4];
#pragma unroll
    for (int i = 0; i < 8; ++i)
#pragma unroll
        for (int j = 0; j < 4; ++j) acc[i][j] = 0ull;

#pragma unroll 8
    for (int k = 0; k < 128; ++k) {
        float4 a0 = *reinterpret_cast<const float4*>(&As[k][tr * 8]);
        float4 a1 = *reinterpret_cast<const float4*>(&As[k][tr * 8 + 4]);
        unsigned long long bp[4];
        const unsigned long long* brow = Bs2 + k * 64 + tc;
        bp[0] = brow[0];
        bp[1] = brow[16];
        bp[2] = brow[32];
        bp[3] = brow[48];
        float a[8] = {a0.x, a0.y, a0.z, a0.w, a1.x, a1.y, a1.z, a1.w};
#pragma unroll
        for (int i = 0; i < 8; ++i) {
            unsigned long long ap;
            asm("mov.b64 %0, {%1, %2};" : "=l"(ap) : "f"(a[i]), "f"(a[i]));
#pragma unroll
            for (int j = 0; j < 4; ++j)
                asm("fma.rn.f32x2 %0, %1, %2, %0;"
                    : "+l"(acc[i][j]) : "l"(ap), "l"(bp[j]));
        }
    }

    float bdv[8];
#pragma unroll
    for (int j = 0; j < 8; ++j) {
        int c = n0 + tc * 8 + j;
        bdv[j] = (c < N) ? __ldg(bd + c) : 0.f;
    }
#pragma unroll
    for (int i = 0; i < 8; ++i) {
        int row = m0 + tr * 8 + i;
        if (row >= M) continue;
        float v[8];
#pragma unroll
        for (int j = 0; j < 4; ++j) {
            float lo, hi;
            asm("mov.b64 {%0, %1}, %2;" : "=f"(lo), "=f"(hi) : "l"(acc[i][j]));
            v[2 * j] = lo; v[2 * j + 1] = hi;
        }
#pragma unroll
        for (int j = 0; j < 8; ++j) {
            float t = v[j] + bdv[j];
            v[j] = __fdividef(1.0f, 1.0f + __expf(-t));
        }
        size_t base = (size_t)row * N + n0 + tc * 8;
        if (fullN) {
            *reinterpret_cast<float4*>(&out[base]) =
                make_float4(v[0], v[1], v[2], v[3]);
            *reinterpret_cast<float4*>(&out[base + 4]) =
                make_float4(v[4], v[5], v[6], v[7]);
        } else {
#pragma unroll
            for (int j = 0; j < 8; ++j) {
                int c = n0 + tc * 8 + j;
                if (c < N) out[(size_t)row * N + c] = v[j];
            }
        }
    }
}

#define DEC_SMEM_BYTES (128 * 128 * 4 + 128 * 64 * 8)   // 131072

// ========================== launch =========================================
extern "C" void kernel_launch(void* const* d_in, const int* in_sizes, int n_in,
                              void* d_out, int out_size)
{
    const float* x     = (const float*)d_in[0];
    const void*  ei    = d_in[1];
    const float* W_enc = (const float*)d_in[2];
    const float* b_enc = (const float*)d_in[3];
    const float* W_dec = (const float*)d_in[4];
    const float* b_dec = (const float*)d_in[5];
    float*       out   = (float*)d_out;

    const int M = in_sizes[5];        // 10000
    int E = in_sizes[1] / 2;          // 320000
    if (E > MAX_E) E = MAX_E;

    detect_kernel<<<1, 128>>>(ei, M);
    convert_edges_kernel<<<(2 * E + 255) / 256, 256>>>(ei, E);

    {   // encoder GEMM, split-K=2: 158 CTAs (full chip)
        dim3 grid(2, (M + 127) / 128);
        encode_gemm_kernel<<<grid, 256>>>(x, W_enc, M);
    }
    enc_init_kernel<<<(M * HID + 255) / 256, 256>>>(b_enc, M);
    {
        int wpb = 256 / 32;
        scatter_kernel<<<(E + wpb - 1) / wpb, 256>>>(E);
    }
    {
        static int smem_set = 0;
        if (!smem_set) {
            cudaFuncSetAttribute(decode_kernel,
                                 cudaFuncAttributeMaxDynamicSharedMemorySize,
                                 DEC_SMEM_BYTES);
            smem_set = 1;
        }
        dim3 grid((M + 127) / 128, (M + 127) / 128);
        decode_kernel<<<grid, 256, DEC_SMEM_BYTES>>>(W_dec, b_dec, out, M, M);
    }
}

// round 15
// speedup vs baseline: 1.0903x; 1.0034x over previous
#include <cuda_runtime.h>
#include <cuda_bf16.h>
#include <cstdint>

// ---------------------------------------------------------------------------
// GraphAutoencoder (all-SIMT fp32, f32x2-packed FMA pipe):
//   h   = x @ W_enc                                    [N, 128]
//   deg = in-degree(dst) + 1 (self loop); dinv = rsqrt(deg)
//   enc = sum_{e:(s->d)} h[s]*dinv[s]*dinv[d] + h[i]*dinv[i]^2 + b_enc
//   out = sigmoid(enc @ W_dec + b_dec)                 [N, N]
// R15 = R14 minus the edge-canonicalize pass (deg_count & scatter read the
// raw edge buffer, uniform is64 branch) + h pre-scaled by dinv in enc_init
// (scatter's per-edge norm becomes dinv[dst] only).  6 launches.
// Decoder unchanged: FFMA2 rt=3 banking floor (proven R9 config).
// ---------------------------------------------------------------------------

#define N_NODES  10000
#define MAX_E    320000
#define IN_DIM   512
#define HID      128

__device__ __align__(16) float g_h [N_NODES * HID];   // K-half 0 partial -> h*dinv
__device__ __align__(16) float g_h2[N_NODES * HID];   // K-half 1 partial
__device__ __align__(16) float g_enc[N_NODES * HID];
__device__ float g_deg[N_NODES];
__device__ float g_dinv[N_NODES];
__device__ int   g_is64;

// ========================== 0) dtype detect + deg init =====================
__global__ void detect_kernel(const void* __restrict__ e, int M)
{
    const unsigned long long* p = (const unsigned long long*)e;
    int t = threadIdx.x;                               // 0..127
    unsigned long long v = p[(size_t)t * 2499];        // < 320000 words
    unsigned bad = __ballot_sync(0xFFFFFFFFu, v >= (1ull << 31));
    __shared__ int anybad;
    if (t == 0) anybad = 0;
    __syncthreads();
    if ((t & 31) == 0 && bad) atomicOr(&anybad, 1);
    __syncthreads();
    if (t == 0) g_is64 = anybad ? 0 : 1;
    for (int i = t; i < M; i += 128) g_deg[i] = 1.0f;  // self loop
}

// ========================== 0b) degree count (raw edge buffer) =============
__global__ void deg_count_kernel(const void* __restrict__ e, int E)
{
    int t = blockIdx.x * blockDim.x + threadIdx.x;
    if (t >= E) return;
    int d;
    if (g_is64) d = (int)((const long long*)e)[E + t];
    else        d = ((const int*)e)[E + t];
    if ((unsigned)d < (unsigned)N_NODES) atomicAdd(&g_deg[d], 1.0f);
}

// ========================== 1) encoder GEMM (split-K=2, BM=128) ============
#define EN_BK 8
__global__ __launch_bounds__(256)
void encode_gemm_kernel(const float* __restrict__ A,   // x
                        const float* __restrict__ B,   // W_enc
                        int M)
{
    __shared__ float As[EN_BK][128];
    __shared__ float Bs[EN_BK][128];

    const int tid = threadIdx.x;
    const int m0  = blockIdx.y * 128;
    const int k0  = blockIdx.x * (IN_DIM / 2);
    float* __restrict__ dst = (blockIdx.x == 0) ? g_h : g_h2;

    const int aRow = tid >> 1;
    const int aCol = (tid & 1) * 4;
    const int bRow = tid >> 5;
    const int bCol = (tid & 31) * 4;
    const int tr = tid >> 4;
    const int tc = tid & 15;
    const bool aOK = (m0 + aRow < M);

    unsigned long long acc[8][4];
#pragma unroll
    for (int i = 0; i < 8; ++i)
#pragma unroll
        for (int j = 0; j < 4; ++j) acc[i][j] = 0ull;

    for (int kk = k0; kk < k0 + IN_DIM / 2; kk += EN_BK) {
        float4 av = make_float4(0.f, 0.f, 0.f, 0.f);
        if (aOK)
            av = *reinterpret_cast<const float4*>(
                     &A[(size_t)(m0 + aRow) * IN_DIM + kk + aCol]);
        As[aCol + 0][aRow] = av.x;
        As[aCol + 1][aRow] = av.y;
        As[aCol + 2][aRow] = av.z;
        As[aCol + 3][aRow] = av.w;
        float4 bv = *reinterpret_cast<const float4*>(
                        &B[(size_t)(kk + bRow) * HID + bCol]);
        *reinterpret_cast<float4*>(&Bs[bRow][bCol]) = bv;
        __syncthreads();

#pragma unroll
        for (int k = 0; k < EN_BK; ++k) {
            float4 a0 = *reinterpret_cast<const float4*>(&As[k][tr * 8]);
            float4 a1 = *reinterpret_cast<const float4*>(&As[k][tr * 8 + 4]);
            float4 b0 = *reinterpret_cast<const float4*>(&Bs[k][tc * 8]);
            float4 b1 = *reinterpret_cast<const float4*>(&Bs[k][tc * 8 + 4]);
            unsigned long long bp[4];
            asm("mov.b64 %0, {%1, %2};" : "=l"(bp[0]) : "f"(b0.x), "f"(b0.y));
            asm("mov.b64 %0, {%1, %2};" : "=l"(bp[1]) : "f"(b0.z), "f"(b0.w));
            asm("mov.b64 %0, {%1, %2};" : "=l"(bp[2]) : "f"(b1.x), "f"(b1.y));
            asm("mov.b64 %0, {%1, %2};" : "=l"(bp[3]) : "f"(b1.z), "f"(b1.w));
            float a[8] = {a0.x, a0.y, a0.z, a0.w, a1.x, a1.y, a1.z, a1.w};
#pragma unroll
            for (int i = 0; i < 8; ++i) {
                unsigned long long ap;
                asm("mov.b64 %0, {%1, %2};" : "=l"(ap) : "f"(a[i]), "f"(a[i]));
#pragma unroll
                for (int j = 0; j < 4; ++j)
                    asm("fma.rn.f32x2 %0, %1, %2, %0;"
                        : "+l"(acc[i][j]) : "l"(ap), "l"(bp[j]));
            }
        }
        __syncthreads();
    }

#pragma unroll
    for (int i = 0; i < 8; ++i) {
        int row = m0 + tr * 8 + i;
        if (row >= M) continue;
        float v[8];
#pragma unroll
        for (int j = 0; j < 4; ++j) {
            float lo, hi;
            asm("mov.b64 {%0, %1}, %2;" : "=f"(lo), "=f"(hi) : "l"(acc[i][j]));
            v[2 * j] = lo; v[2 * j + 1] = hi;
        }
        size_t base = (size_t)row * HID + tc * 8;
        *reinterpret_cast<float4*>(&dst[base]) =
            make_float4(v[0], v[1], v[2], v[3]);
        *reinterpret_cast<float4*>(&dst[base + 4]) =
            make_float4(v[4], v[5], v[6], v[7]);
    }
}

// ========================== 3) enc init: combine + scale + self-loop =======
// sum  = h0 + h1 (split-K combine)
// g_h  <- sum * dinv[i]          (pre-scaled for scatter: msg = g_h[s]*dinv[d])
// enc  <- sum * dinv^2 + b_enc
__global__ void enc_init_kernel(const float* __restrict__ b_enc, int M)
{
    int t = blockIdx.x * blockDim.x + threadIdx.x;
    if (t >= M * HID) return;
    int i = t >> 7;
    int j = t & (HID - 1);
    float sum = g_h[t] + g_h2[t];
    float di = rsqrtf(g_deg[i]);
    if (j == 0) g_dinv[i] = di;
    float hs = sum * di;
    g_h[t]   = hs;                 // pre-scaled
    g_enc[t] = hs * di + b_enc[j]; // = sum*di*di + b
}

// ========================== 4) edge scatter (raw edges, atomic) ============
__global__ void scatter_kernel(const void* __restrict__ e, int E)
{
    int warp = (blockIdx.x * blockDim.x + threadIdx.x) >> 5;
    int lane = threadIdx.x & 31;
    if (warp >= E) return;
    int s, d;
    if (g_is64) {
        const long long* p = (const long long*)e;
        s = (int)p[warp];
        d = (int)p[E + warp];
    } else {
        const int* p = (const int*)e;
        s = p[warp];
        d = p[E + warp];
    }
    if ((unsigned)s >= N_NODES || (unsigned)d >= N_NODES) return;
    float norm = g_dinv[d];        // h already carries dinv[s]
    float4 v = reinterpret_cast<const float4*>(g_h)[(size_t)s * (HID / 4) + lane];
    float* p = g_enc + (size_t)d * HID + lane * 4;
    asm volatile("red.global.add.v4.f32 [%0], {%1, %2, %3, %4};"
                 :: "l"(p), "f"(v.x * norm), "f"(v.y * norm),
                    "f"(v.z * norm), "f"(v.w * norm)
                 : "memory");
}

// ========================== 5) decoder GEMM (R9, proven) ===================
__global__ __launch_bounds__(256, 1)
void decode_kernel(const float* __restrict__ Wd,
                   const float* __restrict__ bd,
                   float* __restrict__ out,
                   int M, int N)
{
    extern __shared__ float dsm[];
    float              (*As)[128] = (float(*)[128])dsm;            // [128][128]
    unsigned long long* Bs2 = (unsigned long long*)(dsm + 128 * 128);

    const int tid = threadIdx.x;
    const int m0  = blockIdx.y * 128;
    const int n0  = blockIdx.x * 128;
    const int tr  = tid >> 4;
    const int tc  = tid & 15;
    const bool fullN = (n0 + 128 <= N);

    {
        const int m   = tid >> 1;
        const int cb  = (tid & 1) * 4;
        const bool ok = (m0 + m < M);
        const float* src = &g_enc[(size_t)(m0 + m) * HID];
#pragma unroll
        for (int kk = 0; kk < 16; ++kk) {
            int col = kk * 8 + cb;
            float4 av = make_float4(0.f, 0.f, 0.f, 0.f);
            if (ok) av = *reinterpret_cast<const float4*>(src + col);
            As[col + 0][m] = av.x;
            As[col + 1][m] = av.y;
            As[col + 2][m] = av.z;
            As[col + 3][m] = av.w;
        }
    }
#pragma unroll
    for (int jj = 0; jj < 16; ++jj) {
        int idx4 = jj * 256 + tid;
        int k    = idx4 >> 5;
        int nq   = idx4 & 31;
        float4 bv;
        if (fullN) {
            bv = *reinterpret_cast<const float4*>(
                     &Wd[(size_t)k * N + n0 + nq * 4]);
        } else {
            float t[4];
#pragma unroll
            for (int i = 0; i < 4; ++i) {
                int c = n0 + nq * 4 + i;
                t[i] = (c < N) ? Wd[(size_t)k * N + c] : 0.f;
            }
            bv = make_float4(t[0], t[1], t[2], t[3]);
        }
        unsigned long long p0, p1;
        asm("mov.b64 %0, {%1, %2};" : "=l"(p0) : "f"(bv.x), "f"(bv.y));
        asm("mov.b64 %0, {%1, %2};" : "=l"(p1) : "f"(bv.z), "f"(bv.w));
        int u0 = k * 64 + ((nq & 1) * 2) * 16 + (nq >> 1);
        Bs2[u0]      = p0;
        Bs2[u0 + 16] = p1;
    }
    __syncthreads();

    unsigned long long acc[8][4];
#pragma unroll
    for (int i = 0; i < 8; ++i)
#pragma unroll
        for (int j = 0; j < 4; ++j) acc[i][j] = 0ull;

#pragma unroll 8
    for (int k = 0; k < 128; ++k) {
        float4 a0 = *reinterpret_cast<const float4*>(&As[k][tr * 8]);
        float4 a1 = *reinterpret_cast<const float4*>(&As[k][tr * 8 + 4]);
        unsigned long long bp[4];
        const unsigned long long* brow = Bs2 + k * 64 + tc;
        bp[0] = brow[0];
        bp[1] = brow[16];
        bp[2] = brow[32];
        bp[3] = brow[48];
        float a[8] = {a0.x, a0.y, a0.z, a0.w, a1.x, a1.y, a1.z, a1.w};
#pragma unroll
        for (int i = 0; i < 8; ++i) {
            unsigned long long ap;
            asm("mov.b64 %0, {%1, %2};" : "=l"(ap) : "f"(a[i]), "f"(a[i]));
#pragma unroll
            for (int j = 0; j < 4; ++j)
                asm("fma.rn.f32x2 %0, %1, %2, %0;"
                    : "+l"(acc[i][j]) : "l"(ap), "l"(bp[j]));
        }
    }

    float bdv[8];
#pragma unroll
    for (int j = 0; j < 8; ++j) {
        int c = n0 + tc * 8 + j;
        bdv[j] = (c < N) ? __ldg(bd + c) : 0.f;
    }
#pragma unroll
    for (int i = 0; i < 8; ++i) {
        int row = m0 + tr * 8 + i;
        if (row >= M) continue;
        float v[8];
#pragma unroll
        for (int j = 0; j < 4; ++j) {
            float lo, hi;
            asm("mov.b64 {%0, %1}, %2;" : "=f"(lo), "=f"(hi) : "l"(acc[i][j]));
            v[2 * j] = lo; v[2 * j + 1] = hi;
        }
#pragma unroll
        for (int j = 0; j < 8; ++j) {
            float t = v[j] + bdv[j];
            v[j] = __fdividef(1.0f, 1.0f + __expf(-t));
        }
        size_t base = (size_t)row * N + n0 + tc * 8;
        if (fullN) {
            *reinterpret_cast<float4*>(&out[base]) =
                make_float4(v[0], v[1], v[2], v[3]);
            *reinterpret_cast<float4*>(&out[base + 4]) =
                make_float4(v[4], v[5], v[6], v[7]);
        } else {
#pragma unroll
            for (int j = 0; j < 8; ++j) {
                int c = n0 + tc * 8 + j;
                if (c < N) out[(size_t)row * N + c] = v[j];
            }
        }
    }
}

#define DEC_SMEM_BYTES (128 * 128 * 4 + 128 * 64 * 8)   // 131072

// ========================== launch =========================================
extern "C" void kernel_launch(void* const* d_in, const int* in_sizes, int n_in,
                              void* d_out, int out_size)
{
    const float* x     = (const float*)d_in[0];
    const void*  ei    = d_in[1];
    const float* W_enc = (const float*)d_in[2];
    const float* b_enc = (const float*)d_in[3];
    const float* W_dec = (const float*)d_in[4];
    const float* b_dec = (const float*)d_in[5];
    float*       out   = (float*)d_out;

    const int M = in_sizes[5];        // 10000
    int E = in_sizes[1] / 2;          // 320000
    if (E > MAX_E) E = MAX_E;

    detect_kernel   <<<1, 128>>>(ei, M);
    deg_count_kernel<<<(E + 255) / 256, 256>>>(ei, E);

    {   // encoder GEMM, split-K=2: 158 CTAs (full chip)
        dim3 grid(2, (M + 127) / 128);
        encode_gemm_kernel<<<grid, 256>>>(x, W_enc, M);
    }
    enc_init_kernel<<<(M * HID + 255) / 256, 256>>>(b_enc, M);
    {
        int wpb = 256 / 32;
        scatter_kernel<<<(E + wpb - 1) / wpb, 256>>>(ei, E);
    }
    {
        static int smem_set = 0;
        if (!smem_set) {
            cudaFuncSetAttribute(decode_kernel,
                                 cudaFuncAttributeMaxDynamicSharedMemorySize,
                                 DEC_SMEM_BYTES);
            smem_set = 1;
        }
        dim3 grid((M + 127) / 128, (M + 127) / 128);
        decode_kernel<<<grid, 256, DEC_SMEM_BYTES>>>(W_dec, b_dec, out, M, M);
    }
}

// round 16
// speedup vs baseline: 1.3193x; 1.2100x over previous
#include <cuda_runtime.h>
#include <cuda_bf16.h>
#include <cstdint>

// ---------------------------------------------------------------------------
// GraphAutoencoder (all-SIMT fp32, f32x2-packed FMA pipe):
//   h   = x @ W_enc                                    [N, 128]
//   deg = in-degree(dst) + 1 (self loop); dinv = rsqrt(deg)
//   enc = sum_{e:(s->d)} h[s]*dinv[s]*dinv[d] + h[i]*dinv[i]^2 + b_enc
//   out = sigmoid(enc @ W_dec + b_dec)                 [N, N]
// R16 = R15 + decoder at 2 CTAs/SM: K staged in two 64-chunks (64 KB smem)
// so one CTA's staging/epilogue overlaps the other's FFMA2 mainloop.
// Mainloop instruction stream identical to the proven R9 loop.
// ---------------------------------------------------------------------------

#define N_NODES  10000
#define MAX_E    320000
#define IN_DIM   512
#define HID      128

__device__ __align__(16) float g_h [N_NODES * HID];   // K-half 0 partial -> h*dinv
__device__ __align__(16) float g_h2[N_NODES * HID];   // K-half 1 partial
__device__ __align__(16) float g_enc[N_NODES * HID];
__device__ float g_deg[N_NODES];
__device__ float g_dinv[N_NODES];
__device__ int   g_is64;

// ========================== 0) dtype detect + deg init =====================
__global__ void detect_kernel(const void* __restrict__ e, int M)
{
    const unsigned long long* p = (const unsigned long long*)e;
    int t = threadIdx.x;                               // 0..127
    unsigned long long v = p[(size_t)t * 2499];        // < 320000 words
    unsigned bad = __ballot_sync(0xFFFFFFFFu, v >= (1ull << 31));
    __shared__ int anybad;
    if (t == 0) anybad = 0;
    __syncthreads();
    if ((t & 31) == 0 && bad) atomicOr(&anybad, 1);
    __syncthreads();
    if (t == 0) g_is64 = anybad ? 0 : 1;
    for (int i = t; i < M; i += 128) g_deg[i] = 1.0f;  // self loop
}

// ========================== 0b) degree count (raw edge buffer) =============
__global__ void deg_count_kernel(const void* __restrict__ e, int E)
{
    int t = blockIdx.x * blockDim.x + threadIdx.x;
    if (t >= E) return;
    int d;
    if (g_is64) d = (int)((const long long*)e)[E + t];
    else        d = ((const int*)e)[E + t];
    if ((unsigned)d < (unsigned)N_NODES) atomicAdd(&g_deg[d], 1.0f);
}

// ========================== 1) encoder GEMM (split-K=2, BM=128) ============
#define EN_BK 8
__global__ __launch_bounds__(256)
void encode_gemm_kernel(const float* __restrict__ A,   // x
                        const float* __restrict__ B,   // W_enc
                        int M)
{
    __shared__ float As[EN_BK][128];
    __shared__ float Bs[EN_BK][128];

    const int tid = threadIdx.x;
    const int m0  = blockIdx.y * 128;
    const int k0  = blockIdx.x * (IN_DIM / 2);
    float* __restrict__ dst = (blockIdx.x == 0) ? g_h : g_h2;

    const int aRow = tid >> 1;
    const int aCol = (tid & 1) * 4;
    const int bRow = tid >> 5;
    const int bCol = (tid & 31) * 4;
    const int tr = tid >> 4;
    const int tc = tid & 15;
    const bool aOK = (m0 + aRow < M);

    unsigned long long acc[8][4];
#pragma unroll
    for (int i = 0; i < 8; ++i)
#pragma unroll
        for (int j = 0; j < 4; ++j) acc[i][j] = 0ull;

    for (int kk = k0; kk < k0 + IN_DIM / 2; kk += EN_BK) {
        float4 av = make_float4(0.f, 0.f, 0.f, 0.f);
        if (aOK)
            av = *reinterpret_cast<const float4*>(
                     &A[(size_t)(m0 + aRow) * IN_DIM + kk + aCol]);
        As[aCol + 0][aRow] = av.x;
        As[aCol + 1][aRow] = av.y;
        As[aCol + 2][aRow] = av.z;
        As[aCol + 3][aRow] = av.w;
        float4 bv = *reinterpret_cast<const float4*>(
                        &B[(size_t)(kk + bRow) * HID + bCol]);
        *reinterpret_cast<float4*>(&Bs[bRow][bCol]) = bv;
        __syncthreads();

#pragma unroll
        for (int k = 0; k < EN_BK; ++k) {
            float4 a0 = *reinterpret_cast<const float4*>(&As[k][tr * 8]);
            float4 a1 = *reinterpret_cast<const float4*>(&As[k][tr * 8 + 4]);
            float4 b0 = *reinterpret_cast<const float4*>(&Bs[k][tc * 8]);
            float4 b1 = *reinterpret_cast<const float4*>(&Bs[k][tc * 8 + 4]);
            unsigned long long bp[4];
            asm("mov.b64 %0, {%1, %2};" : "=l"(bp[0]) : "f"(b0.x), "f"(b0.y));
            asm("mov.b64 %0, {%1, %2};" : "=l"(bp[1]) : "f"(b0.z), "f"(b0.w));
            asm("mov.b64 %0, {%1, %2};" : "=l"(bp[2]) : "f"(b1.x), "f"(b1.y));
            asm("mov.b64 %0, {%1, %2};" : "=l"(bp[3]) : "f"(b1.z), "f"(b1.w));
            float a[8] = {a0.x, a0.y, a0.z, a0.w, a1.x, a1.y, a1.z, a1.w};
#pragma unroll
            for (int i = 0; i < 8; ++i) {
                unsigned long long ap;
                asm("mov.b64 %0, {%1, %2};" : "=l"(ap) : "f"(a[i]), "f"(a[i]));
#pragma unroll
                for (int j = 0; j < 4; ++j)
                    asm("fma.rn.f32x2 %0, %1, %2, %0;"
                        : "+l"(acc[i][j]) : "l"(ap), "l"(bp[j]));
            }
        }
        __syncthreads();
    }

#pragma unroll
    for (int i = 0; i < 8; ++i) {
        int row = m0 + tr * 8 + i;
        if (row >= M) continue;
        float v[8];
#pragma unroll
        for (int j = 0; j < 4; ++j) {
            float lo, hi;
            asm("mov.b64 {%0, %1}, %2;" : "=f"(lo), "=f"(hi) : "l"(acc[i][j]));
            v[2 * j] = lo; v[2 * j + 1] = hi;
        }
        size_t base = (size_t)row * HID + tc * 8;
        *reinterpret_cast<float4*>(&dst[base]) =
            make_float4(v[0], v[1], v[2], v[3]);
        *reinterpret_cast<float4*>(&dst[base + 4]) =
            make_float4(v[4], v[5], v[6], v[7]);
    }
}

// ========================== 3) enc init: combine + scale + self-loop =======
__global__ void enc_init_kernel(const float* __restrict__ b_enc, int M)
{
    int t = blockIdx.x * blockDim.x + threadIdx.x;
    if (t >= M * HID) return;
    int i = t >> 7;
    int j = t & (HID - 1);
    float sum = g_h[t] + g_h2[t];
    float di = rsqrtf(g_deg[i]);
    if (j == 0) g_dinv[i] = di;
    float hs = sum * di;
    g_h[t]   = hs;                 // pre-scaled by dinv[src]
    g_enc[t] = hs * di + b_enc[j]; // = sum*di*di + b
}

// ========================== 4) edge scatter (raw edges, atomic) ============
__global__ void scatter_kernel(const void* __restrict__ e, int E)
{
    int warp = (blockIdx.x * blockDim.x + threadIdx.x) >> 5;
    int lane = threadIdx.x & 31;
    if (warp >= E) return;
    int s, d;
    if (g_is64) {
        const long long* p = (const long long*)e;
        s = (int)p[warp];
        d = (int)p[E + warp];
    } else {
        const int* p = (const int*)e;
        s = p[warp];
        d = p[E + warp];
    }
    if ((unsigned)s >= N_NODES || (unsigned)d >= N_NODES) return;
    float norm = g_dinv[d];        // h already carries dinv[src]
    float4 v = reinterpret_cast<const float4*>(g_h)[(size_t)s * (HID / 4) + lane];
    float* p = g_enc + (size_t)d * HID + lane * 4;
    asm volatile("red.global.add.v4.f32 [%0], {%1, %2, %3, %4};"
                 :: "l"(p), "f"(v.x * norm), "f"(v.y * norm),
                    "f"(v.z * norm), "f"(v.w * norm)
                 : "memory");
}

// ========================== 5) decoder GEMM (R9 loop, 2 CTAs/SM) ===========
// K staged in 2 chunks of 64: As[64][128] (32 KB) + Bs2 chunk (32 KB).
#define DEC_KC 64
__global__ __launch_bounds__(256, 2)
void decode_kernel(const float* __restrict__ Wd,
                   const float* __restrict__ bd,
                   float* __restrict__ out,
                   int M, int N)
{
    __shared__ float              As[DEC_KC][128];              // 32 KB
    __shared__ unsigned long long Bs2[DEC_KC * 64];             // 32 KB

    const int tid = threadIdx.x;
    const int m0  = blockIdx.y * 128;
    const int n0  = blockIdx.x * 128;
    const int tr  = tid >> 4;
    const int tc  = tid & 15;
    const bool fullN = (n0 + 128 <= N);

    unsigned long long acc[8][4];
#pragma unroll
    for (int i = 0; i < 8; ++i)
#pragma unroll
        for (int j = 0; j < 4; ++j) acc[i][j] = 0ull;

    for (int kc = 0; kc < HID; kc += DEC_KC) {
        // --- stage A chunk (transpose): row m=tid>>1, half (tid&1)*4 ---
        {
            const int m   = tid >> 1;
            const int cb  = (tid & 1) * 4;
            const bool ok = (m0 + m < M);
            const float* src = &g_enc[(size_t)(m0 + m) * HID + kc];
#pragma unroll
            for (int kk = 0; kk < DEC_KC / 8; ++kk) {
                int col = kk * 8 + cb;
                float4 av = make_float4(0.f, 0.f, 0.f, 0.f);
                if (ok) av = *reinterpret_cast<const float4*>(src + col);
                As[col + 0][m] = av.x;
                As[col + 1][m] = av.y;
                As[col + 2][m] = av.z;
                As[col + 3][m] = av.w;
            }
        }
        // --- stage B chunk as packed u64 pairs ---
#pragma unroll
        for (int jj = 0; jj < DEC_KC / 8; ++jj) {
            int idx4 = jj * 256 + tid;         // 2048 float4 per chunk
            int k    = idx4 >> 5;              // 0..63
            int nq   = idx4 & 31;
            float4 bv;
            if (fullN) {
                bv = *reinterpret_cast<const float4*>(
                         &Wd[(size_t)(kc + k) * N + n0 + nq * 4]);
            } else {
                float t[4];
#pragma unroll
                for (int i = 0; i < 4; ++i) {
                    int c = n0 + nq * 4 + i;
                    t[i] = (c < N) ? Wd[(size_t)(kc + k) * N + c] : 0.f;
                }
                bv = make_float4(t[0], t[1], t[2], t[3]);
            }
            unsigned long long p0, p1;
            asm("mov.b64 %0, {%1, %2};" : "=l"(p0) : "f"(bv.x), "f"(bv.y));
            asm("mov.b64 %0, {%1, %2};" : "=l"(p1) : "f"(bv.z), "f"(bv.w));
            int u0 = k * 64 + ((nq & 1) * 2) * 16 + (nq >> 1);
            Bs2[u0]      = p0;
            Bs2[u0 + 16] = p1;
        }
        __syncthreads();

        // --- mainloop: DEC_KC k-steps (identical stream to R9) ---
#pragma unroll 8
        for (int k = 0; k < DEC_KC; ++k) {
            float4 a0 = *reinterpret_cast<const float4*>(&As[k][tr * 8]);
            float4 a1 = *reinterpret_cast<const float4*>(&As[k][tr * 8 + 4]);
            unsigned long long bp[4];
            const unsigned long long* brow = Bs2 + k * 64 + tc;
            bp[0] = brow[0];
            bp[1] = brow[16];
            bp[2] = brow[32];
            bp[3] = brow[48];
            float a[8] = {a0.x, a0.y, a0.z, a0.w, a1.x, a1.y, a1.z, a1.w};
#pragma unroll
            for (int i = 0; i < 8; ++i) {
                unsigned long long ap;
                asm("mov.b64 %0, {%1, %2};" : "=l"(ap) : "f"(a[i]), "f"(a[i]));
#pragma unroll
                for (int j = 0; j < 4; ++j)
                    asm("fma.rn.f32x2 %0, %1, %2, %0;"
                        : "+l"(acc[i][j]) : "l"(ap), "l"(bp[j]));
            }
        }
        __syncthreads();
    }

    // --- epilogue: bias + sigmoid ---
    float bdv[8];
#pragma unroll
    for (int j = 0; j < 8; ++j) {
        int c = n0 + tc * 8 + j;
        bdv[j] = (c < N) ? __ldg(bd + c) : 0.f;
    }
#pragma unroll
    for (int i = 0; i < 8; ++i) {
        int row = m0 + tr * 8 + i;
        if (row >= M) continue;
        float v[8];
#pragma unroll
        for (int j = 0; j < 4; ++j) {
            float lo, hi;
            asm("mov.b64 {%0, %1}, %2;" : "=f"(lo), "=f"(hi) : "l"(acc[i][j]));
            v[2 * j] = lo; v[2 * j + 1] = hi;
        }
#pragma unroll
        for (int j = 0; j < 8; ++j) {
            float t = v[j] + bdv[j];
            v[j] = __fdividef(1.0f, 1.0f + __expf(-t));
        }
        size_t base = (size_t)row * N + n0 + tc * 8;
        if (fullN) {
            *reinterpret_cast<float4*>(&out[base]) =
                make_float4(v[0], v[1], v[2], v[3]);
            *reinterpret_cast<float4*>(&out[base + 4]) =
                make_float4(v[4], v[5], v[6], v[7]);
        } else {
#pragma unroll
            for (int j = 0; j < 8; ++j) {
                int c = n0 + tc * 8 + j;
                if (c < N) out[(size_t)row * N + c] = v[j];
            }
        }
    }
}

// ========================== launch =========================================
extern "C" void kernel_launch(void* const* d_in, const int* in_sizes, int n_in,
                              void* d_out, int out_size)
{
    const float* x     = (const float*)d_in[0];
    const void*  ei    = d_in[1];
    const float* W_enc = (const float*)d_in[2];
    const float* b_enc = (const float*)d_in[3];
    const float* W_dec = (const float*)d_in[4];
    const float* b_dec = (const float*)d_in[5];
    float*       out   = (float*)d_out;

    const int M = in_sizes[5];        // 10000
    int E = in_sizes[1] / 2;          // 320000
    if (E > MAX_E) E = MAX_E;

    detect_kernel   <<<1, 128>>>(ei, M);
    deg_count_kernel<<<(E + 255) / 256, 256>>>(ei, E);

    {   // encoder GEMM, split-K=2: 158 CTAs (full chip)
        dim3 grid(2, (M + 127) / 128);
        encode_gemm_kernel<<<grid, 256>>>(x, W_enc, M);
    }
    enc_init_kernel<<<(M * HID + 255) / 256, 256>>>(b_enc, M);
    {
        int wpb = 256 / 32;
        scatter_kernel<<<(E + wpb - 1) / wpb, 256>>>(ei, E);
    }
    {
        dim3 grid((M + 127) / 128, (M + 127) / 128);
        decode_kernel<<<grid, 256>>>(W_dec, b_dec, out, M, M);
    }
}